// round 6
// baseline (speedup 1.0000x reference)
#include <cuda_runtime.h>
#include <cuda_bf16.h>
#include <cuda_fp16.h>
#include <cstdint>

#define TOKENS 131072            // 8 * 128 * 128
#define DIM 256

// scale * log2(e) folded into Q at GEMM0 epilogue
#define K2SCALE 0.25503837897544077f

// ---------------------------------------------------------------------------
// Scratch (device globals — no cudaMalloc allowed)
// ---------------------------------------------------------------------------
__device__ __nv_bfloat16 g_xn[(size_t)TOKENS * DIM];          //  64 MiB
__device__ __nv_bfloat16 g_qkv[(size_t)TOKENS * 3 * DIM];     // 192 MiB (V range holds f16 bits)
__device__ __nv_bfloat16 g_h[(size_t)TOKENS * DIM];           //  64 MiB
__device__ __nv_bfloat16 g_WqkvT[3 * DIM * DIM];              // [768][256]
__device__ __nv_bfloat16 g_WprojT[DIM * DIM];                 // [256][256]

// ---------------------------------------------------------------------------
// PTX helpers
// ---------------------------------------------------------------------------
__device__ __forceinline__ void mma_bf16(float* c, const uint32_t* a, const uint32_t* b) {
    asm volatile(
        "mma.sync.aligned.m16n8k16.row.col.f32.bf16.bf16.f32 "
        "{%0,%1,%2,%3}, {%4,%5,%6,%7}, {%8,%9}, {%0,%1,%2,%3};\n"
        : "+f"(c[0]), "+f"(c[1]), "+f"(c[2]), "+f"(c[3])
        : "r"(a[0]), "r"(a[1]), "r"(a[2]), "r"(a[3]), "r"(b[0]), "r"(b[1]));
}

__device__ __forceinline__ void mma_f16(float* c, const uint32_t* a, const uint32_t* b) {
    asm volatile(
        "mma.sync.aligned.m16n8k16.row.col.f32.f16.f16.f32 "
        "{%0,%1,%2,%3}, {%4,%5,%6,%7}, {%8,%9}, {%0,%1,%2,%3};\n"
        : "+f"(c[0]), "+f"(c[1]), "+f"(c[2]), "+f"(c[3])
        : "r"(a[0]), "r"(a[1]), "r"(a[2]), "r"(a[3]), "r"(b[0]), "r"(b[1]));
}

__device__ __forceinline__ void ldsm_x4(uint32_t* r, uint32_t addr) {
    asm volatile("ldmatrix.sync.aligned.m8n8.x4.shared.b16 {%0,%1,%2,%3}, [%4];"
                 : "=r"(r[0]), "=r"(r[1]), "=r"(r[2]), "=r"(r[3]) : "r"(addr));
}

__device__ __forceinline__ void ldsm_x4_trans(uint32_t* r, uint32_t addr) {
    asm volatile("ldmatrix.sync.aligned.m8n8.x4.trans.shared.b16 {%0,%1,%2,%3}, [%4];"
                 : "=r"(r[0]), "=r"(r[1]), "=r"(r[2]), "=r"(r[3]) : "r"(addr));
}

__device__ __forceinline__ void cp_async16(void* smem_ptr, const void* gmem_ptr) {
    uint32_t s = (uint32_t)__cvta_generic_to_shared(smem_ptr);
    asm volatile("cp.async.cg.shared.global [%0], [%1], 16;\n" :: "r"(s), "l"(gmem_ptr));
}

// P = exp2({lo, hi}) in f16x2 (cvt packs: first PTX src -> hi, second -> lo)
__device__ __forceinline__ uint32_t exp2_f16x2(float lo, float hi) {
    uint32_t h, r;
    asm("cvt.rn.f16x2.f32 %0, %1, %2;" : "=r"(h) : "f"(hi), "f"(lo));
    asm("ex2.approx.f16x2 %0, %1;" : "=r"(r) : "r"(h));
    return r;
}

__device__ __forceinline__ uint32_t hadd2(uint32_t a, uint32_t b) {
    uint32_t d;
    asm("add.f16x2 %0, %1, %2;" : "=r"(d) : "r"(a), "r"(b));
    return d;
}

// ---------------------------------------------------------------------------
// Weight prep: transpose + convert to bf16 (tiny)
// ---------------------------------------------------------------------------
__global__ void prep_weights(const float* __restrict__ Wqkv, const float* __restrict__ Wproj) {
    int n = blockIdx.x;        // 0..767
    int k = threadIdx.x;       // 0..255
    g_WqkvT[n * DIM + k] = __float2bfloat16(Wqkv[(size_t)k * 768 + n]);
    if (n < DIM)
        g_WprojT[n * DIM + k] = __float2bfloat16(Wproj[(size_t)k * DIM + n]);
}

// ---------------------------------------------------------------------------
// LayerNorm: one warp per token (256 channels), output bf16
// ---------------------------------------------------------------------------
__global__ __launch_bounds__(256) void ln_kernel(const float* __restrict__ x,
                                                 const float* __restrict__ gamma,
                                                 const float* __restrict__ beta) {
    int warp = threadIdx.x >> 5, lane = threadIdx.x & 31;
    size_t tok = (size_t)blockIdx.x * 8 + warp;
    const float* row = x + tok * DIM;
    int c0 = lane * 8;
    float4 v0 = *(const float4*)(row + c0);
    float4 v1 = *(const float4*)(row + c0 + 4);
    float v[8] = {v0.x, v0.y, v0.z, v0.w, v1.x, v1.y, v1.z, v1.w};
    float s = 0.f, sq = 0.f;
#pragma unroll
    for (int i = 0; i < 8; i++) { s += v[i]; sq += v[i] * v[i]; }
#pragma unroll
    for (int o = 16; o > 0; o >>= 1) {
        s  += __shfl_xor_sync(0xffffffffu, s, o);
        sq += __shfl_xor_sync(0xffffffffu, sq, o);
    }
    float mean = s * (1.0f / DIM);
    float var  = sq * (1.0f / DIM) - mean * mean;
    float rstd = rsqrtf(var + 1e-5f);
    float4 ga = *(const float4*)(gamma + c0);
    float4 gb = *(const float4*)(gamma + c0 + 4);
    float4 ba = *(const float4*)(beta + c0);
    float4 bb = *(const float4*)(beta + c0 + 4);
    float gg[8] = {ga.x, ga.y, ga.z, ga.w, gb.x, gb.y, gb.z, gb.w};
    float be[8] = {ba.x, ba.y, ba.z, ba.w, bb.x, bb.y, bb.z, bb.w};
    __nv_bfloat16 y[8];
#pragma unroll
    for (int i = 0; i < 8; i++)
        y[i] = __float2bfloat16((v[i] - mean) * rstd * gg[i] + be[i]);
    *(uint4*)(g_xn + tok * DIM + c0) = *(uint4*)y;
}

// ---------------------------------------------------------------------------
// GEMM0 (bf16, persistent over N): qkv[M,768] = xn[M,256] x Wqkv (+bqkv)
// grid = 1024 M-blocks. A tile (128x256, stride 264) loaded ONCE into smem;
// loop over 6 N-tiles x 4 K-blocks with double-buffered B (cp.async).
// Q channels (it 0,1) scaled by K2SCALE; V channels (it 4,5) written as f16.
// smem: A 128x264x2 = 67584 B; B 2 x 128x72x2 = 36864 B; total 104448 B
// ---------------------------------------------------------------------------
#define GEMM0_SMEM 104448

__global__ __launch_bounds__(256, 2) void gemm0_persist(const float* __restrict__ bias) {
    extern __shared__ __nv_bfloat16 sm[];
    // A at elems [0, 33792), B stage s at 33792 + s*9216

    int m0 = blockIdx.x * 128;
    int tid = threadIdx.x;
    int lane = tid & 31, warp = tid >> 5;
    int wm = warp >> 2, wn = warp & 3;   // 2 x 4 warp grid
    int g = lane >> 2, t = lane & 3;

    int arow = lane & 15;
    int acol = (lane >> 4) << 3;
    int brow = (lane & 7) + ((lane >> 4) << 3);
    int bcol = (lane & 8) ? 8 : 0;
    uint32_t smem_u32 = (uint32_t)__cvta_generic_to_shared(sm);
    uint32_t aBase = smem_u32;

    float acc[4][4][4];
#pragma unroll
    for (int i = 0; i < 4; i++)
#pragma unroll
        for (int j = 0; j < 4; j++)
#pragma unroll
            for (int k = 0; k < 4; k++) acc[i][j][k] = 0.f;

    // ---- load A (once): 128 x 256 bf16, stride 264 ----
#pragma unroll
    for (int i = 0; i < 16; i++) {
        int li = tid + i * 256;            // 0..4095
        int row = li >> 5, seg = li & 31;  // 128 rows x 32 segs of 8
        cp_async16(&sm[row * 264 + seg * 8],
                   &g_xn[(size_t)(m0 + row) * 256 + seg * 8]);
    }

    auto load_B = [&](int f, int st) {     // f = flat index -> (it, kb)
        int it = f >> 2, kb = f & 3;
#pragma unroll
        for (int i = 0; i < 4; i++) {
            int li = tid + i * 256;
            int row = li >> 3, seg = li & 7;
            cp_async16(&sm[33792 + st * 9216 + row * 72 + seg * 8],
                       &g_WqkvT[(size_t)(it * 128 + row) * 256 + kb * 64 + seg * 8]);
        }
        asm volatile("cp.async.commit_group;\n" ::: "memory");
    };

    load_B(0, 0);   // group 0 = A + B(0)

    for (int f = 0; f < 24; f++) {
        int it = f >> 2, kb = f & 3, st = f & 1;
        if (f + 1 < 24) {
            load_B(f + 1, (f + 1) & 1);
            asm volatile("cp.async.wait_group 1;\n" ::: "memory");
        } else {
            asm volatile("cp.async.wait_group 0;\n" ::: "memory");
        }
        __syncthreads();

        uint32_t bBase = smem_u32 + (33792 + st * 9216) * 2;

#pragma unroll
        for (int ks = 0; ks < 4; ks++) {
            int kk = kb * 64 + ks * 16;
            uint32_t af[4][4], bfr[4][2];
#pragma unroll
            for (int mt = 0; mt < 4; mt++)
                ldsm_x4(af[mt], aBase + ((wm * 64 + mt * 16 + arow) * 264 + kk + acol) * 2);
#pragma unroll
            for (int p = 0; p < 2; p++) {
                uint32_t r4[4];
                ldsm_x4(r4, bBase + ((wn * 32 + p * 16 + brow) * 72 + ks * 16 + bcol) * 2);
                bfr[2 * p][0] = r4[0]; bfr[2 * p][1] = r4[1];
                bfr[2 * p + 1][0] = r4[2]; bfr[2 * p + 1][1] = r4[3];
            }
#pragma unroll
            for (int mt = 0; mt < 4; mt++)
#pragma unroll
                for (int nt = 0; nt < 4; nt++)
                    mma_bf16(acc[mt][nt], af[mt], bfr[nt]);
        }

        if (kb == 3) {
            // ---- epilogue for N-tile `it` ----
            int n0 = it * 128;
#pragma unroll
            for (int mt = 0; mt < 4; mt++) {
                int r = m0 + wm * 64 + mt * 16 + g;
#pragma unroll
                for (int nt = 0; nt < 4; nt++) {
                    int c = n0 + wn * 32 + nt * 8 + t * 2;
                    float b0 = bias[c], b1 = bias[c + 1];
                    float v00 = acc[mt][nt][0] + b0, v01 = acc[mt][nt][1] + b1;
                    float v10 = acc[mt][nt][2] + b0, v11 = acc[mt][nt][3] + b1;
                    if (it < 4) {
                        float sc = (it < 2) ? K2SCALE : 1.0f;   // Q scaled, K plain
                        *reinterpret_cast<__nv_bfloat162*>(&g_qkv[(size_t)r * 768 + c]) =
                            __floats2bfloat162_rn(v00 * sc, v01 * sc);
                        *reinterpret_cast<__nv_bfloat162*>(&g_qkv[(size_t)(r + 8) * 768 + c]) =
                            __floats2bfloat162_rn(v10 * sc, v11 * sc);
                    } else {
                        // V channels as f16 bits (consumed by attn PV f16 mma)
                        *reinterpret_cast<__half2*>(&g_qkv[(size_t)r * 768 + c]) =
                            __floats2half2_rn(v00, v01);
                        *reinterpret_cast<__half2*>(&g_qkv[(size_t)(r + 8) * 768 + c]) =
                            __floats2half2_rn(v10, v11);
                    }
#pragma unroll
                    for (int k = 0; k < 4; k++) acc[mt][nt][k] = 0.f;
                }
            }
        }
        __syncthreads();
    }
}

// ---------------------------------------------------------------------------
// GEMM1 (bf16): out[M,256] = h[M,256] x Wproj + bproj + x  (fp32 out)
// ---------------------------------------------------------------------------
#define GEMM1_SMEM 73728

__global__ __launch_bounds__(256, 2) void gemm1_kernel(const float* __restrict__ bias,
                                                       const float* __restrict__ resid,
                                                       float* __restrict__ outf) {
    const __nv_bfloat16* A  = g_h;
    const __nv_bfloat16* Bt = g_WprojT;

    extern __shared__ __nv_bfloat16 sm[];

    int m0 = blockIdx.y * 128;
    int n0 = blockIdx.x * 128;
    int tid = threadIdx.x;
    int lane = tid & 31, warp = tid >> 5;
    int wm = warp >> 2, wn = warp & 3;
    int g = lane >> 2, t = lane & 3;

    int arow = lane & 15;
    int acol = (lane >> 4) << 3;
    int brow = (lane & 7) + ((lane >> 4) << 3);
    int bcol = (lane & 8) ? 8 : 0;
    uint32_t smem_u32 = (uint32_t)__cvta_generic_to_shared(sm);

    float acc[4][4][4];
#pragma unroll
    for (int i = 0; i < 4; i++)
#pragma unroll
        for (int j = 0; j < 4; j++)
#pragma unroll
            for (int k = 0; k < 4; k++) acc[i][j][k] = 0.f;

    auto load_stage = [&](int kb, int s) {
#pragma unroll
        for (int i = 0; i < 4; i++) {
            int li = tid + i * 256;
            int row = li >> 3, seg = li & 7;
            cp_async16(&sm[s * 9216 + row * 72 + seg * 8],
                       &A[(size_t)(m0 + row) * 256 + kb * 64 + seg * 8]);
            cp_async16(&sm[18432 + s * 9216 + row * 72 + seg * 8],
                       &Bt[(size_t)(n0 + row) * 256 + kb * 64 + seg * 8]);
        }
        asm volatile("cp.async.commit_group;\n" ::: "memory");
    };

    load_stage(0, 0);

#pragma unroll
    for (int kb = 0; kb < 4; kb++) {
        if (kb < 3) {
            load_stage(kb + 1, (kb + 1) & 1);
            asm volatile("cp.async.wait_group 1;\n" ::: "memory");
        } else {
            asm volatile("cp.async.wait_group 0;\n" ::: "memory");
        }
        __syncthreads();

        int s = kb & 1;
        uint32_t aBase = smem_u32 + (s * 9216) * 2;
        uint32_t bBase = smem_u32 + (18432 + s * 9216) * 2;

#pragma unroll
        for (int ks = 0; ks < 4; ks++) {
            int kk = ks * 16;
            uint32_t af[4][4], bfr[4][2];
#pragma unroll
            for (int mt = 0; mt < 4; mt++)
                ldsm_x4(af[mt], aBase + ((wm * 64 + mt * 16 + arow) * 72 + kk + acol) * 2);
#pragma unroll
            for (int p = 0; p < 2; p++) {
                uint32_t r4[4];
                ldsm_x4(r4, bBase + ((wn * 32 + p * 16 + brow) * 72 + kk + bcol) * 2);
                bfr[2 * p][0] = r4[0]; bfr[2 * p][1] = r4[1];
                bfr[2 * p + 1][0] = r4[2]; bfr[2 * p + 1][1] = r4[3];
            }
#pragma unroll
            for (int mt = 0; mt < 4; mt++)
#pragma unroll
                for (int nt = 0; nt < 4; nt++)
                    mma_bf16(acc[mt][nt], af[mt], bfr[nt]);
        }
        __syncthreads();
    }

#pragma unroll
    for (int mt = 0; mt < 4; mt++) {
        int r = m0 + wm * 64 + mt * 16 + g;
#pragma unroll
        for (int nt = 0; nt < 4; nt++) {
            int c = n0 + wn * 32 + nt * 8 + t * 2;
            float b0 = bias[c], b1 = bias[c + 1];
            size_t i0 = (size_t)r * 256 + c;
            float2 rx0 = *(const float2*)(resid + i0);
            float2 o0;
            o0.x = acc[mt][nt][0] + b0 + rx0.x;
            o0.y = acc[mt][nt][1] + b1 + rx0.y;
            *(float2*)(outf + i0) = o0;
            size_t i1 = (size_t)(r + 8) * 256 + c;
            float2 rx1 = *(const float2*)(resid + i1);
            float2 o1;
            o1.x = acc[mt][nt][2] + b0 + rx1.x;
            o1.y = acc[mt][nt][3] + b1 + rx1.y;
            *(float2*)(outf + i1) = o1;
        }
    }
}

// ---------------------------------------------------------------------------
// Stripe attention. One block = (branch, batch, stripe-group, head).
// seq = 256, head_dim = 32. 8 warps x 32 q-rows. No-max softmax with
// ex2.approx.f16x2 (2 vals/MUFU op), P directly as f16 mma fragments,
// row sums via HADD2. S-mma bf16, PV-mma f16 (V stored f16 by GEMM0).
// smem: sQ [256][40] bf16 (reused as sO), sK [256][40] bf16,
//       sV [256][40] f16 = 61440 B
// ---------------------------------------------------------------------------
#define ATTN_SMEM 61440

__global__ __launch_bounds__(256, 2) void attn_kernel() {
    extern __shared__ __nv_bfloat16 smA[];
    __nv_bfloat16* sQ = smA;                    // [256][40]  (reused as sO)
    __nv_bfloat16* sK = smA + 10240;            // [256][40]
    __half*        sV = (__half*)(smA + 20480); // [256][40] f16
    __nv_bfloat16* sO = sQ;

    int bid = blockIdx.x;
    int head   = bid & 3;
    int grp    = (bid >> 2) & 63;
    int b      = (bid >> 8) & 7;
    int branch = bid >> 11;                       // 0 = horizontal, 1 = vertical
    int off = branch << 7;                        // 0 or 128
    int chq = off + head * 32;

    int tid = threadIdx.x;
    int lane = tid & 31, warp = tid >> 5;

    // --- load Q, K, V for this (group, head): row-major [seq][32] ---
    {
        int s = tid;  // seq position 0..255
        size_t tok;
        if (branch == 0)
            tok = (size_t)(b * 128 + grp * 2) * 128 + s;
        else
            tok = (size_t)(b * 128 + (s & 127)) * 128 + grp * 2 + (s >> 7);
        const __nv_bfloat16* base = g_qkv + tok * 768;
#pragma unroll
        for (int i = 0; i < 4; i++)
            *(uint4*)&sQ[s * 40 + i * 8] = *(const uint4*)&base[chq + i * 8];
#pragma unroll
        for (int i = 0; i < 4; i++)
            *(uint4*)&sK[s * 40 + i * 8] = *(const uint4*)&base[256 + chq + i * 8];
#pragma unroll
        for (int i = 0; i < 4; i++)
            *(uint4*)&sV[s * 40 + i * 8] = *(const uint4*)&base[512 + chq + i * 8];
    }
    __syncthreads();

    int g = lane >> 2, t = lane & 3;
    int mbase = warp * 32;

    int arow = lane & 15;
    int acol = (lane >> 4) << 3;
    int brow = (lane & 7) + ((lane >> 4) << 3);
    int bcol = (lane & 8) ? 8 : 0;
    uint32_t qBase = (uint32_t)__cvta_generic_to_shared(sQ);
    uint32_t kBase = (uint32_t)__cvta_generic_to_shared(sK);
    uint32_t vBase = (uint32_t)__cvta_generic_to_shared(sV);

    // persistent Q fragments
    uint32_t qa[2][2][4];
#pragma unroll
    for (int mt = 0; mt < 2; mt++)
#pragma unroll
        for (int ks = 0; ks < 2; ks++)
            ldsm_x4(qa[mt][ks],
                    qBase + ((mbase + mt * 16 + arow) * 40 + ks * 16 + acol) * 2);

    float o[2][4][4];
#pragma unroll
    for (int i = 0; i < 2; i++)
#pragma unroll
        for (int j = 0; j < 4; j++)
#pragma unroll
            for (int k = 0; k < 4; k++) o[i][j][k] = 0.f;
    // f16x2 row-sum accumulators: [mt][0]=row g, [mt][1]=row g+8
    uint32_t lsum[2][2] = {{0u, 0u}, {0u, 0u}};

#pragma unroll
    for (int kc = 0; kc < 8; kc++) {
        // S = Q K^T for 32-key chunk
        float sacc[2][4][4];
#pragma unroll
        for (int i = 0; i < 2; i++)
#pragma unroll
            for (int j = 0; j < 4; j++)
#pragma unroll
                for (int k = 0; k < 4; k++) sacc[i][j][k] = 0.f;

#pragma unroll
        for (int ks = 0; ks < 2; ks++) {
            uint32_t kb[4][2];
#pragma unroll
            for (int p = 0; p < 2; p++) {
                uint32_t r4[4];
                ldsm_x4(r4, kBase + ((kc * 32 + p * 16 + brow) * 40 + ks * 16 + bcol) * 2);
                kb[2 * p][0] = r4[0]; kb[2 * p][1] = r4[1];
                kb[2 * p + 1][0] = r4[2]; kb[2 * p + 1][1] = r4[3];
            }
#pragma unroll
            for (int mt = 0; mt < 2; mt++)
#pragma unroll
                for (int nt = 0; nt < 4; nt++)
                    mma_bf16(sacc[mt][nt], qa[mt][ks], kb[nt]);
        }

        // P = exp2(S) as f16x2, directly in mma A-fragment layout; sums via HADD2
        uint32_t pf[2][2][4];   // [mt][ksv][a0..a3]
#pragma unroll
        for (int mt = 0; mt < 2; mt++) {
#pragma unroll
            for (int ksv = 0; ksv < 2; ksv++) {
                pf[mt][ksv][0] = exp2_f16x2(sacc[mt][2 * ksv][0],     sacc[mt][2 * ksv][1]);
                pf[mt][ksv][1] = exp2_f16x2(sacc[mt][2 * ksv][2],     sacc[mt][2 * ksv][3]);
                pf[mt][ksv][2] = exp2_f16x2(sacc[mt][2 * ksv + 1][0], sacc[mt][2 * ksv + 1][1]);
                pf[mt][ksv][3] = exp2_f16x2(sacc[mt][2 * ksv + 1][2], sacc[mt][2 * ksv + 1][3]);
                lsum[mt][0] = hadd2(lsum[mt][0], hadd2(pf[mt][ksv][0], pf[mt][ksv][2]));
                lsum[mt][1] = hadd2(lsum[mt][1], hadd2(pf[mt][ksv][1], pf[mt][ksv][3]));
            }
        }

        // O += P V  (f16 x f16; V^T fragments via ldmatrix.trans)
#pragma unroll
        for (int ksv = 0; ksv < 2; ksv++) {
            uint32_t vb[4][2];
            int vrow = kc * 32 + ksv * 16 + (lane & 15);
#pragma unroll
            for (int p = 0; p < 2; p++) {
                uint32_t r4[4];
                ldsm_x4_trans(r4, vBase + (vrow * 40 + p * 16 + ((lane >> 4) << 3)) * 2);
                vb[2 * p][0] = r4[0]; vb[2 * p][1] = r4[1];
                vb[2 * p + 1][0] = r4[2]; vb[2 * p + 1][1] = r4[3];
            }
#pragma unroll
            for (int mt = 0; mt < 2; mt++)
#pragma unroll
                for (int nt = 0; nt < 4; nt++)
                    mma_f16(o[mt][nt], pf[mt][ksv], vb[nt]);
        }
    }

    // final row-sum reduce, normalize, stage to smem (bf16)
#pragma unroll
    for (int mt = 0; mt < 2; mt++)
#pragma unroll
        for (int hi = 0; hi < 2; hi++) {
            __half2 h2 = *reinterpret_cast<__half2*>(&lsum[mt][hi]);
            float l = __low2float(h2) + __high2float(h2);
            l += __shfl_xor_sync(0xffffffffu, l, 1);
            l += __shfl_xor_sync(0xffffffffu, l, 2);
            float inv = 1.0f / l;
            int r = mbase + mt * 16 + g + hi * 8;
#pragma unroll
            for (int nt = 0; nt < 4; nt++) {
                *reinterpret_cast<__nv_bfloat162*>(&sO[r * 40 + nt * 8 + t * 2]) =
                    __floats2bfloat162_rn(o[mt][nt][hi * 2] * inv, o[mt][nt][hi * 2 + 1] * inv);
            }
        }
    __syncthreads();

    // cooperative coalesced write to g_h
#pragma unroll
    for (int i = 0; i < 4; i++) {
        int li = i * 256 + tid;
        int s = li >> 2, seg = li & 3;
        size_t tok;
        if (branch == 0)
            tok = (size_t)(b * 128 + grp * 2) * 128 + s;
        else
            tok = (size_t)(b * 128 + (s & 127)) * 128 + grp * 2 + (s >> 7);
        *(uint4*)&g_h[tok * 256 + chq + seg * 8] = *(const uint4*)&sO[s * 40 + seg * 8];
    }
}

// ---------------------------------------------------------------------------
// launch
// ---------------------------------------------------------------------------
extern "C" void kernel_launch(void* const* d_in, const int* in_sizes, int n_in,
                              void* d_out, int out_size) {
    const float* x     = (const float*)d_in[0];
    const float* Wqkv  = (const float*)d_in[1];
    const float* bqkv  = (const float*)d_in[2];
    const float* Wproj = (const float*)d_in[3];
    const float* bproj = (const float*)d_in[4];
    const float* gamma = (const float*)d_in[5];
    const float* beta  = (const float*)d_in[6];
    float* out = (float*)d_out;

    cudaFuncSetAttribute(gemm0_persist, cudaFuncAttributeMaxDynamicSharedMemorySize, GEMM0_SMEM);
    cudaFuncSetAttribute(gemm1_kernel, cudaFuncAttributeMaxDynamicSharedMemorySize, GEMM1_SMEM);
    cudaFuncSetAttribute(attn_kernel, cudaFuncAttributeMaxDynamicSharedMemorySize, ATTN_SMEM);

    prep_weights<<<768, 256>>>(Wqkv, Wproj);
    ln_kernel<<<TOKENS / 8, 256>>>(x, gamma, beta);
    gemm0_persist<<<TOKENS / 128, 256, GEMM0_SMEM>>>(bqkv);
    attn_kernel<<<4096, 256, ATTN_SMEM>>>();
    gemm1_kernel<<<dim3(2, TOKENS / 128), 256, GEMM1_SMEM>>>(bproj, x, out);
}

// round 7
// speedup vs baseline: 1.0484x; 1.0484x over previous
#include <cuda_runtime.h>
#include <cuda_bf16.h>
#include <cstdint>

#define TOKENS 131072            // 8 * 128 * 128
#define DIM 256

// scale * log2(e) folded into Q at GEMM0 epilogue
#define K2SCALE 0.25503837897544077f

// ---------------------------------------------------------------------------
// Scratch (device globals — no cudaMalloc allowed)
// ---------------------------------------------------------------------------
__device__ __nv_bfloat16 g_qkv[(size_t)TOKENS * 3 * DIM];     // 192 MiB
__device__ __nv_bfloat16 g_h[(size_t)TOKENS * DIM];           //  64 MiB
__device__ __nv_bfloat16 g_WqkvT[3 * DIM * DIM];              // [768][256]
__device__ __nv_bfloat16 g_WprojT[DIM * DIM];                 // [256][256]

// ---------------------------------------------------------------------------
// PTX helpers
// ---------------------------------------------------------------------------
__device__ __forceinline__ void mma_bf16(float* c, const uint32_t* a, const uint32_t* b) {
    asm volatile(
        "mma.sync.aligned.m16n8k16.row.col.f32.bf16.bf16.f32 "
        "{%0,%1,%2,%3}, {%4,%5,%6,%7}, {%8,%9}, {%0,%1,%2,%3};\n"
        : "+f"(c[0]), "+f"(c[1]), "+f"(c[2]), "+f"(c[3])
        : "r"(a[0]), "r"(a[1]), "r"(a[2]), "r"(a[3]), "r"(b[0]), "r"(b[1]));
}

__device__ __forceinline__ void ldsm_x4(uint32_t* r, uint32_t addr) {
    asm volatile("ldmatrix.sync.aligned.m8n8.x4.shared.b16 {%0,%1,%2,%3}, [%4];"
                 : "=r"(r[0]), "=r"(r[1]), "=r"(r[2]), "=r"(r[3]) : "r"(addr));
}

__device__ __forceinline__ void cp_async16(void* smem_ptr, const void* gmem_ptr) {
    uint32_t s = (uint32_t)__cvta_generic_to_shared(smem_ptr);
    asm volatile("cp.async.cg.shared.global [%0], [%1], 16;\n" :: "r"(s), "l"(gmem_ptr));
}

__device__ __forceinline__ uint32_t pack_bf(float x, float y) {
    __nv_bfloat162 h = __floats2bfloat162_rn(x, y);
    return *reinterpret_cast<uint32_t*>(&h);
}

// ---------------------------------------------------------------------------
// Weight prep: transpose + convert to bf16 (tiny)
// ---------------------------------------------------------------------------
__global__ void prep_weights(const float* __restrict__ Wqkv, const float* __restrict__ Wproj) {
    int n = blockIdx.x;        // 0..767
    int k = threadIdx.x;       // 0..255
    g_WqkvT[n * DIM + k] = __float2bfloat16(Wqkv[(size_t)k * 768 + n]);
    if (n < DIM)
        g_WprojT[n * DIM + k] = __float2bfloat16(Wproj[(size_t)k * DIM + n]);
}

// ---------------------------------------------------------------------------
// GEMM0 (bf16, persistent over N, LN fused): qkv[M,768] = LN(x)[M,256] x Wqkv
// grid = 1024 M-blocks. LN computed in the prologue (warp-per-row, 16 rows
// per warp) writing the bf16 A tile (128x256, stride 264) straight to smem,
// overlapped with the first B-tile cp.async. Then loop over 6 N-tiles x 4
// K-blocks with double-buffered B. Q channels (it 0,1) scaled by K2SCALE.
// smem: A 128x264x2 = 67584 B; B 2 x 128x72x2 = 36864 B; total 104448 B
// ---------------------------------------------------------------------------
#define GEMM0_SMEM 104448

__global__ __launch_bounds__(256, 2) void gemm0_persist(const float* __restrict__ x,
                                                        const float* __restrict__ gamma,
                                                        const float* __restrict__ beta,
                                                        const float* __restrict__ bias) {
    extern __shared__ __nv_bfloat16 sm[];
    // A at elems [0, 33792), B stage s at 33792 + s*9216

    int m0 = blockIdx.x * 128;
    int tid = threadIdx.x;
    int lane = tid & 31, warp = tid >> 5;
    int wm = warp >> 2, wn = warp & 3;   // 2 x 4 warp grid
    int g = lane >> 2, t = lane & 3;

    int arow = lane & 15;
    int acol = (lane >> 4) << 3;
    int brow = (lane & 7) + ((lane >> 4) << 3);
    int bcol = (lane & 8) ? 8 : 0;
    uint32_t smem_u32 = (uint32_t)__cvta_generic_to_shared(sm);
    uint32_t aBase = smem_u32;

    auto load_B = [&](int f, int st) {     // f = flat index -> (it, kb)
        int it = f >> 2, kb = f & 3;
#pragma unroll
        for (int i = 0; i < 4; i++) {
            int li = tid + i * 256;
            int row = li >> 3, seg = li & 7;
            cp_async16(&sm[33792 + st * 9216 + row * 72 + seg * 8],
                       &g_WqkvT[(size_t)(it * 128 + row) * 256 + kb * 64 + seg * 8]);
        }
        asm volatile("cp.async.commit_group;\n" ::: "memory");
    };

    load_B(0, 0);   // overlap first B load with LN prologue

    // ---- LN prologue: 8 warps x 16 rows, write bf16 A tile to smem ----
    {
        int c0 = lane * 8;
        float4 ga = *(const float4*)(gamma + c0);
        float4 gb = *(const float4*)(gamma + c0 + 4);
        float4 ba = *(const float4*)(beta + c0);
        float4 bb = *(const float4*)(beta + c0 + 4);
        float gg[8] = {ga.x, ga.y, ga.z, ga.w, gb.x, gb.y, gb.z, gb.w};
        float be[8] = {ba.x, ba.y, ba.z, ba.w, bb.x, bb.y, bb.z, bb.w};
#pragma unroll 4
        for (int i = 0; i < 16; i++) {
            int row = warp * 16 + i;
            const float* xr = x + (size_t)(m0 + row) * 256 + c0;
            float4 v0 = *(const float4*)xr;
            float4 v1 = *(const float4*)(xr + 4);
            float v[8] = {v0.x, v0.y, v0.z, v0.w, v1.x, v1.y, v1.z, v1.w};
            float s = 0.f, sq = 0.f;
#pragma unroll
            for (int j = 0; j < 8; j++) { s += v[j]; sq += v[j] * v[j]; }
#pragma unroll
            for (int o = 16; o > 0; o >>= 1) {
                s  += __shfl_xor_sync(0xffffffffu, s, o);
                sq += __shfl_xor_sync(0xffffffffu, sq, o);
            }
            float mean = s * (1.0f / DIM);
            float var  = sq * (1.0f / DIM) - mean * mean;
            float rstd = rsqrtf(var + 1e-5f);
            __nv_bfloat16 y[8];
#pragma unroll
            for (int j = 0; j < 8; j++)
                y[j] = __float2bfloat16((v[j] - mean) * rstd * gg[j] + be[j]);
            *(uint4*)&sm[row * 264 + c0] = *(uint4*)y;
        }
    }

    float acc[4][4][4];
#pragma unroll
    for (int i = 0; i < 4; i++)
#pragma unroll
        for (int j = 0; j < 4; j++)
#pragma unroll
            for (int k = 0; k < 4; k++) acc[i][j][k] = 0.f;

    for (int f = 0; f < 24; f++) {
        int it = f >> 2, kb = f & 3, st = f & 1;
        if (f + 1 < 24) {
            load_B(f + 1, (f + 1) & 1);
            asm volatile("cp.async.wait_group 1;\n" ::: "memory");
        } else {
            asm volatile("cp.async.wait_group 0;\n" ::: "memory");
        }
        __syncthreads();

        uint32_t bBase = smem_u32 + (33792 + st * 9216) * 2;

#pragma unroll
        for (int ks = 0; ks < 4; ks++) {
            int kk = kb * 64 + ks * 16;
            uint32_t af[4][4], bfr[4][2];
#pragma unroll
            for (int mt = 0; mt < 4; mt++)
                ldsm_x4(af[mt], aBase + ((wm * 64 + mt * 16 + arow) * 264 + kk + acol) * 2);
#pragma unroll
            for (int p = 0; p < 2; p++) {
                uint32_t r4[4];
                ldsm_x4(r4, bBase + ((wn * 32 + p * 16 + brow) * 72 + ks * 16 + bcol) * 2);
                bfr[2 * p][0] = r4[0]; bfr[2 * p][1] = r4[1];
                bfr[2 * p + 1][0] = r4[2]; bfr[2 * p + 1][1] = r4[3];
            }
#pragma unroll
            for (int mt = 0; mt < 4; mt++)
#pragma unroll
                for (int nt = 0; nt < 4; nt++)
                    mma_bf16(acc[mt][nt], af[mt], bfr[nt]);
        }

        if (kb == 3) {
            int n0 = it * 128;
            float sc = (it < 2) ? K2SCALE : 1.0f;   // Q scaled; K, V plain
#pragma unroll
            for (int mt = 0; mt < 4; mt++) {
                int r = m0 + wm * 64 + mt * 16 + g;
#pragma unroll
                for (int nt = 0; nt < 4; nt++) {
                    int c = n0 + wn * 32 + nt * 8 + t * 2;
                    float b0 = bias[c], b1 = bias[c + 1];
                    *reinterpret_cast<__nv_bfloat162*>(&g_qkv[(size_t)r * 768 + c]) =
                        __floats2bfloat162_rn((acc[mt][nt][0] + b0) * sc,
                                              (acc[mt][nt][1] + b1) * sc);
                    *reinterpret_cast<__nv_bfloat162*>(&g_qkv[(size_t)(r + 8) * 768 + c]) =
                        __floats2bfloat162_rn((acc[mt][nt][2] + b0) * sc,
                                              (acc[mt][nt][3] + b1) * sc);
#pragma unroll
                    for (int k = 0; k < 4; k++) acc[mt][nt][k] = 0.f;
                }
            }
        }
        __syncthreads();
    }
}

// ---------------------------------------------------------------------------
// GEMM1 (bf16, persistent over N): out[M,256] = h[M,256] x Wproj + bproj + x
// grid = 1024 M-blocks; A (g_h) tile loaded once; 2 N-tiles x 4 K-blocks
// with double-buffered B. fp32 output with residual.
// ---------------------------------------------------------------------------
#define GEMM1_SMEM 104448

__global__ __launch_bounds__(256, 2) void gemm1_persist(const float* __restrict__ bias,
                                                        const float* __restrict__ resid,
                                                        float* __restrict__ outf) {
    extern __shared__ __nv_bfloat16 sm[];

    int m0 = blockIdx.x * 128;
    int tid = threadIdx.x;
    int lane = tid & 31, warp = tid >> 5;
    int wm = warp >> 2, wn = warp & 3;
    int g = lane >> 2, t = lane & 3;

    int arow = lane & 15;
    int acol = (lane >> 4) << 3;
    int brow = (lane & 7) + ((lane >> 4) << 3);
    int bcol = (lane & 8) ? 8 : 0;
    uint32_t smem_u32 = (uint32_t)__cvta_generic_to_shared(sm);
    uint32_t aBase = smem_u32;

    // ---- load A (once): 128 x 256 bf16, stride 264 ----
#pragma unroll
    for (int i = 0; i < 16; i++) {
        int li = tid + i * 256;
        int row = li >> 5, seg = li & 31;
        cp_async16(&sm[row * 264 + seg * 8],
                   &g_h[(size_t)(m0 + row) * 256 + seg * 8]);
    }

    auto load_B = [&](int f, int st) {
        int it = f >> 2, kb = f & 3;
#pragma unroll
        for (int i = 0; i < 4; i++) {
            int li = tid + i * 256;
            int row = li >> 3, seg = li & 7;
            cp_async16(&sm[33792 + st * 9216 + row * 72 + seg * 8],
                       &g_WprojT[(size_t)(it * 128 + row) * 256 + kb * 64 + seg * 8]);
        }
        asm volatile("cp.async.commit_group;\n" ::: "memory");
    };

    load_B(0, 0);

    float acc[4][4][4];
#pragma unroll
    for (int i = 0; i < 4; i++)
#pragma unroll
        for (int j = 0; j < 4; j++)
#pragma unroll
            for (int k = 0; k < 4; k++) acc[i][j][k] = 0.f;

    for (int f = 0; f < 8; f++) {
        int it = f >> 2, kb = f & 3, st = f & 1;
        if (f + 1 < 8) {
            load_B(f + 1, (f + 1) & 1);
            asm volatile("cp.async.wait_group 1;\n" ::: "memory");
        } else {
            asm volatile("cp.async.wait_group 0;\n" ::: "memory");
        }
        __syncthreads();

        uint32_t bBase = smem_u32 + (33792 + st * 9216) * 2;

#pragma unroll
        for (int ks = 0; ks < 4; ks++) {
            int kk = kb * 64 + ks * 16;
            uint32_t af[4][4], bfr[4][2];
#pragma unroll
            for (int mt = 0; mt < 4; mt++)
                ldsm_x4(af[mt], aBase + ((wm * 64 + mt * 16 + arow) * 264 + kk + acol) * 2);
#pragma unroll
            for (int p = 0; p < 2; p++) {
                uint32_t r4[4];
                ldsm_x4(r4, bBase + ((wn * 32 + p * 16 + brow) * 72 + ks * 16 + bcol) * 2);
                bfr[2 * p][0] = r4[0]; bfr[2 * p][1] = r4[1];
                bfr[2 * p + 1][0] = r4[2]; bfr[2 * p + 1][1] = r4[3];
            }
#pragma unroll
            for (int mt = 0; mt < 4; mt++)
#pragma unroll
                for (int nt = 0; nt < 4; nt++)
                    mma_bf16(acc[mt][nt], af[mt], bfr[nt]);
        }

        if (kb == 3) {
            int n0 = it * 128;
#pragma unroll
            for (int mt = 0; mt < 4; mt++) {
                int r = m0 + wm * 64 + mt * 16 + g;
#pragma unroll
                for (int nt = 0; nt < 4; nt++) {
                    int c = n0 + wn * 32 + nt * 8 + t * 2;
                    float b0 = bias[c], b1 = bias[c + 1];
                    size_t i0 = (size_t)r * 256 + c;
                    float2 rx0 = *(const float2*)(resid + i0);
                    float2 o0;
                    o0.x = acc[mt][nt][0] + b0 + rx0.x;
                    o0.y = acc[mt][nt][1] + b1 + rx0.y;
                    *(float2*)(outf + i0) = o0;
                    size_t i1 = (size_t)(r + 8) * 256 + c;
                    float2 rx1 = *(const float2*)(resid + i1);
                    float2 o1;
                    o1.x = acc[mt][nt][2] + b0 + rx1.x;
                    o1.y = acc[mt][nt][3] + b1 + rx1.y;
                    *(float2*)(outf + i1) = o1;
#pragma unroll
                    for (int k = 0; k < 4; k++) acc[mt][nt][k] = 0.f;
                }
            }
        }
        __syncthreads();
    }
}

// ---------------------------------------------------------------------------
// Stripe attention (round-4 measured-best). One block = (branch, batch,
// stripe-group, head). seq = 256, head_dim = 32. 8 warps x 32 q-rows.
// No-max softmax, fp32 exp2f; scale*log2e pre-folded into Q by GEMM0.
// smem: sQ [256][40] (reused as sO), sK [256][40], sVt [32][264] = 57856 B
// ---------------------------------------------------------------------------
#define ATTN_SMEM 57856

__global__ __launch_bounds__(256, 2) void attn_kernel() {
    extern __shared__ __nv_bfloat16 smA[];
    __nv_bfloat16* sQ  = smA;                    // [256][40]  (reused as sO)
    __nv_bfloat16* sK  = smA + 10240;            // [256][40]
    __nv_bfloat16* sVt = smA + 20480;            // [32][264]  (V transposed)
    __nv_bfloat16* sO  = sQ;

    int bid = blockIdx.x;
    int head   = bid & 3;
    int grp    = (bid >> 2) & 63;
    int b      = (bid >> 8) & 7;
    int branch = bid >> 11;                       // 0 = horizontal, 1 = vertical
    int off = branch << 7;                        // 0 or 128
    int chq = off + head * 32;

    int tid = threadIdx.x;
    int lane = tid & 31, warp = tid >> 5;

    // --- load Q, K, V(transposed) for this (group, head) ---
    {
        int s = tid;  // seq position 0..255
        size_t tok;
        if (branch == 0)
            tok = (size_t)(b * 128 + grp * 2) * 128 + s;
        else
            tok = (size_t)(b * 128 + (s & 127)) * 128 + grp * 2 + (s >> 7);
        const __nv_bfloat16* base = g_qkv + tok * 768;
#pragma unroll
        for (int i = 0; i < 4; i++)
            *(uint4*)&sQ[s * 40 + i * 8] = *(const uint4*)&base[chq + i * 8];
#pragma unroll
        for (int i = 0; i < 4; i++)
            *(uint4*)&sK[s * 40 + i * 8] = *(const uint4*)&base[256 + chq + i * 8];
        __nv_bfloat16 vv[32];
#pragma unroll
        for (int i = 0; i < 4; i++)
            *(uint4*)&vv[i * 8] = *(const uint4*)&base[512 + chq + i * 8];
#pragma unroll
        for (int d = 0; d < 32; d++)
            sVt[d * 264 + s] = vv[d];
    }
    __syncthreads();

    int g = lane >> 2, t = lane & 3;
    int mbase = warp * 32;

    int arow = lane & 15;
    int acol = (lane >> 4) << 3;
    int brow = (lane & 7) + ((lane >> 4) << 3);
    int bcol = (lane & 8) ? 8 : 0;
    uint32_t qBase = (uint32_t)__cvta_generic_to_shared(sQ);
    uint32_t kBase = (uint32_t)__cvta_generic_to_shared(sK);
    uint32_t vBase = (uint32_t)__cvta_generic_to_shared(sVt);

    // persistent Q fragments (warp's 32 rows x k=32)
    uint32_t qa[2][2][4];
#pragma unroll
    for (int mt = 0; mt < 2; mt++)
#pragma unroll
        for (int ks = 0; ks < 2; ks++)
            ldsm_x4(qa[mt][ks],
                    qBase + ((mbase + mt * 16 + arow) * 40 + ks * 16 + acol) * 2);

    float o[2][4][4];
#pragma unroll
    for (int i = 0; i < 2; i++)
#pragma unroll
        for (int j = 0; j < 4; j++)
#pragma unroll
            for (int k = 0; k < 4; k++) o[i][j][k] = 0.f;
    float lrow[2][2] = {{0.f, 0.f}, {0.f, 0.f}};

#pragma unroll
    for (int kc = 0; kc < 8; kc++) {
        float sacc[2][4][4];
#pragma unroll
        for (int i = 0; i < 2; i++)
#pragma unroll
            for (int j = 0; j < 4; j++)
#pragma unroll
                for (int k = 0; k < 4; k++) sacc[i][j][k] = 0.f;

#pragma unroll
        for (int ks = 0; ks < 2; ks++) {
            uint32_t kb[4][2];
#pragma unroll
            for (int p = 0; p < 2; p++) {
                uint32_t r4[4];
                ldsm_x4(r4, kBase + ((kc * 32 + p * 16 + brow) * 40 + ks * 16 + bcol) * 2);
                kb[2 * p][0] = r4[0]; kb[2 * p][1] = r4[1];
                kb[2 * p + 1][0] = r4[2]; kb[2 * p + 1][1] = r4[3];
            }
#pragma unroll
            for (int mt = 0; mt < 2; mt++)
#pragma unroll
                for (int nt = 0; nt < 4; nt++)
                    mma_bf16(sacc[mt][nt], qa[mt][ks], kb[nt]);
        }

        // P = exp2(S)
#pragma unroll
        for (int mt = 0; mt < 2; mt++)
#pragma unroll
            for (int hi = 0; hi < 2; hi++) {
                float rs = 0.f;
#pragma unroll
                for (int nt = 0; nt < 4; nt++) {
                    float p0 = exp2f(sacc[mt][nt][hi * 2]);
                    float p1 = exp2f(sacc[mt][nt][hi * 2 + 1]);
                    sacc[mt][nt][hi * 2] = p0;
                    sacc[mt][nt][hi * 2 + 1] = p1;
                    rs += p0 + p1;
                }
                lrow[mt][hi] += rs;
            }

        // O += P V
#pragma unroll
        for (int ksv = 0; ksv < 2; ksv++) {
            uint32_t pa[2][4];
#pragma unroll
            for (int mt = 0; mt < 2; mt++) {
                pa[mt][0] = pack_bf(sacc[mt][2 * ksv][0], sacc[mt][2 * ksv][1]);
                pa[mt][1] = pack_bf(sacc[mt][2 * ksv][2], sacc[mt][2 * ksv][3]);
                pa[mt][2] = pack_bf(sacc[mt][2 * ksv + 1][0], sacc[mt][2 * ksv + 1][1]);
                pa[mt][3] = pack_bf(sacc[mt][2 * ksv + 1][2], sacc[mt][2 * ksv + 1][3]);
            }
            uint32_t vb[4][2];
            int kkv = kc * 32 + ksv * 16;
#pragma unroll
            for (int p = 0; p < 2; p++) {
                uint32_t r4[4];
                ldsm_x4(r4, vBase + ((p * 16 + brow) * 264 + kkv + bcol) * 2);
                vb[2 * p][0] = r4[0]; vb[2 * p][1] = r4[1];
                vb[2 * p + 1][0] = r4[2]; vb[2 * p + 1][1] = r4[3];
            }
#pragma unroll
            for (int mt = 0; mt < 2; mt++)
#pragma unroll
                for (int nt = 0; nt < 4; nt++)
                    mma_bf16(o[mt][nt], pa[mt], vb[nt]);
        }
    }

    // final row-sum reduce, normalize, stage to smem (bf16)
#pragma unroll
    for (int mt = 0; mt < 2; mt++)
#pragma unroll
        for (int hi = 0; hi < 2; hi++) {
            float l = lrow[mt][hi];
            l += __shfl_xor_sync(0xffffffffu, l, 1);
            l += __shfl_xor_sync(0xffffffffu, l, 2);
            float inv = 1.0f / l;
            int r = mbase + mt * 16 + g + hi * 8;
#pragma unroll
            for (int nt = 0; nt < 4; nt++) {
                *reinterpret_cast<__nv_bfloat162*>(&sO[r * 40 + nt * 8 + t * 2]) =
                    __floats2bfloat162_rn(o[mt][nt][hi * 2] * inv, o[mt][nt][hi * 2 + 1] * inv);
            }
        }
    __syncthreads();

    // cooperative coalesced write to g_h
#pragma unroll
    for (int i = 0; i < 4; i++) {
        int li = i * 256 + tid;
        int s = li >> 2, seg = li & 3;
        size_t tok;
        if (branch == 0)
            tok = (size_t)(b * 128 + grp * 2) * 128 + s;
        else
            tok = (size_t)(b * 128 + (s & 127)) * 128 + grp * 2 + (s >> 7);
        *(uint4*)&g_h[tok * 256 + chq + seg * 8] = *(const uint4*)&sO[s * 40 + seg * 8];
    }
}

// ---------------------------------------------------------------------------
// launch
// ---------------------------------------------------------------------------
extern "C" void kernel_launch(void* const* d_in, const int* in_sizes, int n_in,
                              void* d_out, int out_size) {
    const float* x     = (const float*)d_in[0];
    const float* Wqkv  = (const float*)d_in[1];
    const float* bqkv  = (const float*)d_in[2];
    const float* Wproj = (const float*)d_in[3];
    const float* bproj = (const float*)d_in[4];
    const float* gamma = (const float*)d_in[5];
    const float* beta  = (const float*)d_in[6];
    float* out = (float*)d_out;

    cudaFuncSetAttribute(gemm0_persist, cudaFuncAttributeMaxDynamicSharedMemorySize, GEMM0_SMEM);
    cudaFuncSetAttribute(gemm1_persist, cudaFuncAttributeMaxDynamicSharedMemorySize, GEMM1_SMEM);
    cudaFuncSetAttribute(attn_kernel, cudaFuncAttributeMaxDynamicSharedMemorySize, ATTN_SMEM);

    prep_weights<<<768, 256>>>(Wqkv, Wproj);
    gemm0_persist<<<TOKENS / 128, 256, GEMM0_SMEM>>>(x, gamma, beta, bqkv);
    attn_kernel<<<4096, 256, ATTN_SMEM>>>();
    gemm1_persist<<<TOKENS / 128, 256, GEMM1_SMEM>>>(bproj, x, out);
}

// round 8
// speedup vs baseline: 1.0535x; 1.0049x over previous
#include <cuda_runtime.h>
#include <cuda_bf16.h>
#include <cstdint>

#define TOKENS 131072            // 8 * 128 * 128
#define DIM 256

// scale * log2(e) folded into Q at GEMM0 epilogue
#define K2SCALE 0.25503837897544077f

// ---------------------------------------------------------------------------
// Scratch (device globals — no cudaMalloc allowed)
// ---------------------------------------------------------------------------
__device__ __nv_bfloat16 g_qkv[(size_t)TOKENS * 3 * DIM];     // 192 MiB
__device__ __nv_bfloat16 g_h[(size_t)TOKENS * DIM];           //  64 MiB
__device__ __nv_bfloat16 g_WqkvT[3 * DIM * DIM];              // [768][256]
__device__ __nv_bfloat16 g_WprojT[DIM * DIM];                 // [256][256]

// ---------------------------------------------------------------------------
// PTX helpers
// ---------------------------------------------------------------------------
__device__ __forceinline__ void mma_bf16(float* c, const uint32_t* a, const uint32_t* b) {
    asm volatile(
        "mma.sync.aligned.m16n8k16.row.col.f32.bf16.bf16.f32 "
        "{%0,%1,%2,%3}, {%4,%5,%6,%7}, {%8,%9}, {%0,%1,%2,%3};\n"
        : "+f"(c[0]), "+f"(c[1]), "+f"(c[2]), "+f"(c[3])
        : "r"(a[0]), "r"(a[1]), "r"(a[2]), "r"(a[3]), "r"(b[0]), "r"(b[1]));
}

__device__ __forceinline__ void ldsm_x4(uint32_t* r, uint32_t addr) {
    asm volatile("ldmatrix.sync.aligned.m8n8.x4.shared.b16 {%0,%1,%2,%3}, [%4];"
                 : "=r"(r[0]), "=r"(r[1]), "=r"(r[2]), "=r"(r[3]) : "r"(addr));
}

__device__ __forceinline__ void cp_async16(void* smem_ptr, const void* gmem_ptr) {
    uint32_t s = (uint32_t)__cvta_generic_to_shared(smem_ptr);
    asm volatile("cp.async.cg.shared.global [%0], [%1], 16;\n" :: "r"(s), "l"(gmem_ptr));
}

__device__ __forceinline__ uint32_t pack_bf(float x, float y) {
    __nv_bfloat162 h = __floats2bfloat162_rn(x, y);
    return *reinterpret_cast<uint32_t*>(&h);
}

// force the MUFU fast path regardless of compiler fast-math flags
__device__ __forceinline__ float ex2_fast(float x) {
    float y;
    asm("ex2.approx.f32 %0, %1;" : "=f"(y) : "f"(x));
    return y;
}

// ---------------------------------------------------------------------------
// Weight prep: transpose + convert to bf16 (tiny)
// ---------------------------------------------------------------------------
__global__ void prep_weights(const float* __restrict__ Wqkv, const float* __restrict__ Wproj) {
    int n = blockIdx.x;        // 0..767
    int k = threadIdx.x;       // 0..255
    g_WqkvT[n * DIM + k] = __float2bfloat16(Wqkv[(size_t)k * 768 + n]);
    if (n < DIM)
        g_WprojT[n * DIM + k] = __float2bfloat16(Wproj[(size_t)k * DIM + n]);
}

// ---------------------------------------------------------------------------
// GEMM0 (bf16, persistent over N, LN fused): qkv[M,768] = LN(x)[M,256] x Wqkv
// grid = 1024 M-blocks. LN in the prologue writes the bf16 A tile (128x256,
// stride 264) straight to smem, overlapped with the first B-tile cp.async.
// Then 6 N-tiles x 4 K-blocks, double-buffered B, SINGLE barrier/iter:
//   wait_group 0 -> __syncthreads -> issue load_B(f+1) -> mma(stage f&1)
// Q channels (it 0,1) scaled by K2SCALE.
// smem: A 128x264x2 = 67584 B; B 2 x 128x72x2 = 36864 B; total 104448 B
// ---------------------------------------------------------------------------
#define GEMM0_SMEM 104448

__global__ __launch_bounds__(256, 2) void gemm0_persist(const float* __restrict__ x,
                                                        const float* __restrict__ gamma,
                                                        const float* __restrict__ beta,
                                                        const float* __restrict__ bias) {
    extern __shared__ __nv_bfloat16 sm[];
    // A at elems [0, 33792), B stage s at 33792 + s*9216

    int m0 = blockIdx.x * 128;
    int tid = threadIdx.x;
    int lane = tid & 31, warp = tid >> 5;
    int wm = warp >> 2, wn = warp & 3;   // 2 x 4 warp grid
    int g = lane >> 2, t = lane & 3;

    int arow = lane & 15;
    int acol = (lane >> 4) << 3;
    int brow = (lane & 7) + ((lane >> 4) << 3);
    int bcol = (lane & 8) ? 8 : 0;
    uint32_t smem_u32 = (uint32_t)__cvta_generic_to_shared(sm);
    uint32_t aBase = smem_u32;

    auto load_B = [&](int f, int st) {     // f = flat index -> (it, kb)
        int it = f >> 2, kb = f & 3;
#pragma unroll
        for (int i = 0; i < 4; i++) {
            int li = tid + i * 256;
            int row = li >> 3, seg = li & 7;
            cp_async16(&sm[33792 + st * 9216 + row * 72 + seg * 8],
                       &g_WqkvT[(size_t)(it * 128 + row) * 256 + kb * 64 + seg * 8]);
        }
        asm volatile("cp.async.commit_group;\n" ::: "memory");
    };

    load_B(0, 0);   // overlap first B load with LN prologue

    // ---- LN prologue: 8 warps x 16 rows, write bf16 A tile to smem ----
    {
        int c0 = lane * 8;
        float4 ga = *(const float4*)(gamma + c0);
        float4 gb = *(const float4*)(gamma + c0 + 4);
        float4 ba = *(const float4*)(beta + c0);
        float4 bb = *(const float4*)(beta + c0 + 4);
        float gg[8] = {ga.x, ga.y, ga.z, ga.w, gb.x, gb.y, gb.z, gb.w};
        float be[8] = {ba.x, ba.y, ba.z, ba.w, bb.x, bb.y, bb.z, bb.w};
#pragma unroll 4
        for (int i = 0; i < 16; i++) {
            int row = warp * 16 + i;
            const float* xr = x + (size_t)(m0 + row) * 256 + c0;
            float4 v0 = *(const float4*)xr;
            float4 v1 = *(const float4*)(xr + 4);
            float v[8] = {v0.x, v0.y, v0.z, v0.w, v1.x, v1.y, v1.z, v1.w};
            float s = 0.f, sq = 0.f;
#pragma unroll
            for (int j = 0; j < 8; j++) { s += v[j]; sq += v[j] * v[j]; }
#pragma unroll
            for (int o = 16; o > 0; o >>= 1) {
                s  += __shfl_xor_sync(0xffffffffu, s, o);
                sq += __shfl_xor_sync(0xffffffffu, sq, o);
            }
            float mean = s * (1.0f / DIM);
            float var  = sq * (1.0f / DIM) - mean * mean;
            float rstd = rsqrtf(var + 1e-5f);
            __nv_bfloat16 y[8];
#pragma unroll
            for (int j = 0; j < 8; j++)
                y[j] = __float2bfloat16((v[j] - mean) * rstd * gg[j] + be[j]);
            *(uint4*)&sm[row * 264 + c0] = *(uint4*)y;
        }
    }

    float acc[4][4][4];
#pragma unroll
    for (int i = 0; i < 4; i++)
#pragma unroll
        for (int j = 0; j < 4; j++)
#pragma unroll
            for (int k = 0; k < 4; k++) acc[i][j][k] = 0.f;

    for (int f = 0; f < 24; f++) {
        int it = f >> 2, kb = f & 3, st = f & 1;
        // all of this thread's pending cp.async groups (i.e. group f) done
        asm volatile("cp.async.wait_group 0;\n" ::: "memory");
        // everyone's group-f data visible; everyone done reading stage (f-1)&1
        __syncthreads();
        if (f + 1 < 24) load_B(f + 1, (f + 1) & 1);  // writes stage (f+1)&1

        uint32_t bBase = smem_u32 + (33792 + st * 9216) * 2;

#pragma unroll
        for (int ks = 0; ks < 4; ks++) {
            int kk = kb * 64 + ks * 16;
            uint32_t af[4][4], bfr[4][2];
#pragma unroll
            for (int mt = 0; mt < 4; mt++)
                ldsm_x4(af[mt], aBase + ((wm * 64 + mt * 16 + arow) * 264 + kk + acol) * 2);
#pragma unroll
            for (int p = 0; p < 2; p++) {
                uint32_t r4[4];
                ldsm_x4(r4, bBase + ((wn * 32 + p * 16 + brow) * 72 + ks * 16 + bcol) * 2);
                bfr[2 * p][0] = r4[0]; bfr[2 * p][1] = r4[1];
                bfr[2 * p + 1][0] = r4[2]; bfr[2 * p + 1][1] = r4[3];
            }
#pragma unroll
            for (int mt = 0; mt < 4; mt++)
#pragma unroll
                for (int nt = 0; nt < 4; nt++)
                    mma_bf16(acc[mt][nt], af[mt], bfr[nt]);
        }

        if (kb == 3) {
            int n0 = it * 128;
            float sc = (it < 2) ? K2SCALE : 1.0f;   // Q scaled; K, V plain
#pragma unroll
            for (int mt = 0; mt < 4; mt++) {
                int r = m0 + wm * 64 + mt * 16 + g;
#pragma unroll
                for (int nt = 0; nt < 4; nt++) {
                    int c = n0 + wn * 32 + nt * 8 + t * 2;
                    float b0 = bias[c], b1 = bias[c + 1];
                    *reinterpret_cast<__nv_bfloat162*>(&g_qkv[(size_t)r * 768 + c]) =
                        __floats2bfloat162_rn((acc[mt][nt][0] + b0) * sc,
                                              (acc[mt][nt][1] + b1) * sc);
                    *reinterpret_cast<__nv_bfloat162*>(&g_qkv[(size_t)(r + 8) * 768 + c]) =
                        __floats2bfloat162_rn((acc[mt][nt][2] + b0) * sc,
                                              (acc[mt][nt][3] + b1) * sc);
#pragma unroll
                    for (int k = 0; k < 4; k++) acc[mt][nt][k] = 0.f;
                }
            }
        }
    }
}

// ---------------------------------------------------------------------------
// GEMM1 (bf16, persistent over N): out[M,256] = h[M,256] x Wproj + bproj + x
// Same single-barrier pipeline; 2 N-tiles x 4 K-blocks. fp32 out + residual.
// ---------------------------------------------------------------------------
#define GEMM1_SMEM 104448

__global__ __launch_bounds__(256, 2) void gemm1_persist(const float* __restrict__ bias,
                                                        const float* __restrict__ resid,
                                                        float* __restrict__ outf) {
    extern __shared__ __nv_bfloat16 sm[];

    int m0 = blockIdx.x * 128;
    int tid = threadIdx.x;
    int lane = tid & 31, warp = tid >> 5;
    int wm = warp >> 2, wn = warp & 3;
    int g = lane >> 2, t = lane & 3;

    int arow = lane & 15;
    int acol = (lane >> 4) << 3;
    int brow = (lane & 7) + ((lane >> 4) << 3);
    int bcol = (lane & 8) ? 8 : 0;
    uint32_t smem_u32 = (uint32_t)__cvta_generic_to_shared(sm);
    uint32_t aBase = smem_u32;

    auto load_B = [&](int f, int st) {
        int it = f >> 2, kb = f & 3;
#pragma unroll
        for (int i = 0; i < 4; i++) {
            int li = tid + i * 256;
            int row = li >> 3, seg = li & 7;
            cp_async16(&sm[33792 + st * 9216 + row * 72 + seg * 8],
                       &g_WprojT[(size_t)(it * 128 + row) * 256 + kb * 64 + seg * 8]);
        }
        asm volatile("cp.async.commit_group;\n" ::: "memory");
    };

    load_B(0, 0);

    // ---- load A (once): 128 x 256 bf16, stride 264 ----
#pragma unroll
    for (int i = 0; i < 16; i++) {
        int li = tid + i * 256;
        int row = li >> 5, seg = li & 31;
        cp_async16(&sm[row * 264 + seg * 8],
                   &g_h[(size_t)(m0 + row) * 256 + seg * 8]);
    }
    asm volatile("cp.async.commit_group;\n" ::: "memory");

    float acc[4][4][4];
#pragma unroll
    for (int i = 0; i < 4; i++)
#pragma unroll
        for (int j = 0; j < 4; j++)
#pragma unroll
            for (int k = 0; k < 4; k++) acc[i][j][k] = 0.f;

    for (int f = 0; f < 8; f++) {
        int it = f >> 2, kb = f & 3, st = f & 1;
        asm volatile("cp.async.wait_group 0;\n" ::: "memory");
        __syncthreads();
        if (f + 1 < 8) load_B(f + 1, (f + 1) & 1);

        uint32_t bBase = smem_u32 + (33792 + st * 9216) * 2;

#pragma unroll
        for (int ks = 0; ks < 4; ks++) {
            int kk = kb * 64 + ks * 16;
            uint32_t af[4][4], bfr[4][2];
#pragma unroll
            for (int mt = 0; mt < 4; mt++)
                ldsm_x4(af[mt], aBase + ((wm * 64 + mt * 16 + arow) * 264 + kk + acol) * 2);
#pragma unroll
            for (int p = 0; p < 2; p++) {
                uint32_t r4[4];
                ldsm_x4(r4, bBase + ((wn * 32 + p * 16 + brow) * 72 + ks * 16 + bcol) * 2);
                bfr[2 * p][0] = r4[0]; bfr[2 * p][1] = r4[1];
                bfr[2 * p + 1][0] = r4[2]; bfr[2 * p + 1][1] = r4[3];
            }
#pragma unroll
            for (int mt = 0; mt < 4; mt++)
#pragma unroll
                for (int nt = 0; nt < 4; nt++)
                    mma_bf16(acc[mt][nt], af[mt], bfr[nt]);
        }

        if (kb == 3) {
            int n0 = it * 128;
#pragma unroll
            for (int mt = 0; mt < 4; mt++) {
                int r = m0 + wm * 64 + mt * 16 + g;
#pragma unroll
                for (int nt = 0; nt < 4; nt++) {
                    int c = n0 + wn * 32 + nt * 8 + t * 2;
                    float b0 = bias[c], b1 = bias[c + 1];
                    size_t i0 = (size_t)r * 256 + c;
                    float2 rx0 = *(const float2*)(resid + i0);
                    float2 o0;
                    o0.x = acc[mt][nt][0] + b0 + rx0.x;
                    o0.y = acc[mt][nt][1] + b1 + rx0.y;
                    *(float2*)(outf + i0) = o0;
                    size_t i1 = (size_t)(r + 8) * 256 + c;
                    float2 rx1 = *(const float2*)(resid + i1);
                    float2 o1;
                    o1.x = acc[mt][nt][2] + b0 + rx1.x;
                    o1.y = acc[mt][nt][3] + b1 + rx1.y;
                    *(float2*)(outf + i1) = o1;
#pragma unroll
                    for (int k = 0; k < 4; k++) acc[mt][nt][k] = 0.f;
                }
            }
        }
    }
}

// ---------------------------------------------------------------------------
// Stripe attention (round-4 measured-best + forced MUFU ex2).
// One block = (branch, batch, stripe-group, head). seq 256, head_dim 32.
// 8 warps x 32 q-rows. No-max softmax; scale*log2e pre-folded into Q.
// smem: sQ [256][40] (reused as sO), sK [256][40], sVt [32][264] = 57856 B
// ---------------------------------------------------------------------------
#define ATTN_SMEM 57856

__global__ __launch_bounds__(256, 2) void attn_kernel() {
    extern __shared__ __nv_bfloat16 smA[];
    __nv_bfloat16* sQ  = smA;                    // [256][40]  (reused as sO)
    __nv_bfloat16* sK  = smA + 10240;            // [256][40]
    __nv_bfloat16* sVt = smA + 20480;            // [32][264]  (V transposed)
    __nv_bfloat16* sO  = sQ;

    int bid = blockIdx.x;
    int head   = bid & 3;
    int grp    = (bid >> 2) & 63;
    int b      = (bid >> 8) & 7;
    int branch = bid >> 11;                       // 0 = horizontal, 1 = vertical
    int off = branch << 7;                        // 0 or 128
    int chq = off + head * 32;

    int tid = threadIdx.x;
    int lane = tid & 31, warp = tid >> 5;

    // --- load Q, K, V(transposed) for this (group, head) ---
    {
        int s = tid;  // seq position 0..255
        size_t tok;
        if (branch == 0)
            tok = (size_t)(b * 128 + grp * 2) * 128 + s;
        else
            tok = (size_t)(b * 128 + (s & 127)) * 128 + grp * 2 + (s >> 7);
        const __nv_bfloat16* base = g_qkv + tok * 768;
#pragma unroll
        for (int i = 0; i < 4; i++)
            *(uint4*)&sQ[s * 40 + i * 8] = *(const uint4*)&base[chq + i * 8];
#pragma unroll
        for (int i = 0; i < 4; i++)
            *(uint4*)&sK[s * 40 + i * 8] = *(const uint4*)&base[256 + chq + i * 8];
        __nv_bfloat16 vv[32];
#pragma unroll
        for (int i = 0; i < 4; i++)
            *(uint4*)&vv[i * 8] = *(const uint4*)&base[512 + chq + i * 8];
#pragma unroll
        for (int d = 0; d < 32; d++)
            sVt[d * 264 + s] = vv[d];
    }
    __syncthreads();

    int g = lane >> 2, t = lane & 3;
    int mbase = warp * 32;

    int arow = lane & 15;
    int acol = (lane >> 4) << 3;
    int brow = (lane & 7) + ((lane >> 4) << 3);
    int bcol = (lane & 8) ? 8 : 0;
    uint32_t qBase = (uint32_t)__cvta_generic_to_shared(sQ);
    uint32_t kBase = (uint32_t)__cvta_generic_to_shared(sK);
    uint32_t vBase = (uint32_t)__cvta_generic_to_shared(sVt);

    // persistent Q fragments (warp's 32 rows x k=32)
    uint32_t qa[2][2][4];
#pragma unroll
    for (int mt = 0; mt < 2; mt++)
#pragma unroll
        for (int ks = 0; ks < 2; ks++)
            ldsm_x4(qa[mt][ks],
                    qBase + ((mbase + mt * 16 + arow) * 40 + ks * 16 + acol) * 2);

    float o[2][4][4];
#pragma unroll
    for (int i = 0; i < 2; i++)
#pragma unroll
        for (int j = 0; j < 4; j++)
#pragma unroll
            for (int k = 0; k < 4; k++) o[i][j][k] = 0.f;
    float lrow[2][2] = {{0.f, 0.f}, {0.f, 0.f}};

#pragma unroll
    for (int kc = 0; kc < 8; kc++) {
        float sacc[2][4][4];
#pragma unroll
        for (int i = 0; i < 2; i++)
#pragma unroll
            for (int j = 0; j < 4; j++)
#pragma unroll
                for (int k = 0; k < 4; k++) sacc[i][j][k] = 0.f;

#pragma unroll
        for (int ks = 0; ks < 2; ks++) {
            uint32_t kb[4][2];
#pragma unroll
            for (int p = 0; p < 2; p++) {
                uint32_t r4[4];
                ldsm_x4(r4, kBase + ((kc * 32 + p * 16 + brow) * 40 + ks * 16 + bcol) * 2);
                kb[2 * p][0] = r4[0]; kb[2 * p][1] = r4[1];
                kb[2 * p + 1][0] = r4[2]; kb[2 * p + 1][1] = r4[3];
            }
#pragma unroll
            for (int mt = 0; mt < 2; mt++)
#pragma unroll
                for (int nt = 0; nt < 4; nt++)
                    mma_bf16(sacc[mt][nt], qa[mt][ks], kb[nt]);
        }

        // P = exp2(S) via MUFU (forced fast path)
#pragma unroll
        for (int mt = 0; mt < 2; mt++)
#pragma unroll
            for (int hi = 0; hi < 2; hi++) {
                float rs = 0.f;
#pragma unroll
                for (int nt = 0; nt < 4; nt++) {
                    float p0 = ex2_fast(sacc[mt][nt][hi * 2]);
                    float p1 = ex2_fast(sacc[mt][nt][hi * 2 + 1]);
                    sacc[mt][nt][hi * 2] = p0;
                    sacc[mt][nt][hi * 2 + 1] = p1;
                    rs += p0 + p1;
                }
                lrow[mt][hi] += rs;
            }

        // O += P V
#pragma unroll
        for (int ksv = 0; ksv < 2; ksv++) {
            uint32_t pa[2][4];
#pragma unroll
            for (int mt = 0; mt < 2; mt++) {
                pa[mt][0] = pack_bf(sacc[mt][2 * ksv][0], sacc[mt][2 * ksv][1]);
                pa[mt][1] = pack_bf(sacc[mt][2 * ksv][2], sacc[mt][2 * ksv][3]);
                pa[mt][2] = pack_bf(sacc[mt][2 * ksv + 1][0], sacc[mt][2 * ksv + 1][1]);
                pa[mt][3] = pack_bf(sacc[mt][2 * ksv + 1][2], sacc[mt][2 * ksv + 1][3]);
            }
            uint32_t vb[4][2];
            int kkv = kc * 32 + ksv * 16;
#pragma unroll
            for (int p = 0; p < 2; p++) {
                uint32_t r4[4];
                ldsm_x4(r4, vBase + ((p * 16 + brow) * 264 + kkv + bcol) * 2);
                vb[2 * p][0] = r4[0]; vb[2 * p][1] = r4[1];
                vb[2 * p + 1][0] = r4[2]; vb[2 * p + 1][1] = r4[3];
            }
#pragma unroll
            for (int mt = 0; mt < 2; mt++)
#pragma unroll
                for (int nt = 0; nt < 4; nt++)
                    mma_bf16(o[mt][nt], pa[mt], vb[nt]);
        }
    }

    // final row-sum reduce, normalize, stage to smem (bf16)
#pragma unroll
    for (int mt = 0; mt < 2; mt++)
#pragma unroll
        for (int hi = 0; hi < 2; hi++) {
            float l = lrow[mt][hi];
            l += __shfl_xor_sync(0xffffffffu, l, 1);
            l += __shfl_xor_sync(0xffffffffu, l, 2);
            float inv = 1.0f / l;
            int r = mbase + mt * 16 + g + hi * 8;
#pragma unroll
            for (int nt = 0; nt < 4; nt++) {
                *reinterpret_cast<__nv_bfloat162*>(&sO[r * 40 + nt * 8 + t * 2]) =
                    __floats2bfloat162_rn(o[mt][nt][hi * 2] * inv, o[mt][nt][hi * 2 + 1] * inv);
            }
        }
    __syncthreads();

    // cooperative coalesced write to g_h
#pragma unroll
    for (int i = 0; i < 4; i++) {
        int li = i * 256 + tid;
        int s = li >> 2, seg = li & 3;
        size_t tok;
        if (branch == 0)
            tok = (size_t)(b * 128 + grp * 2) * 128 + s;
        else
            tok = (size_t)(b * 128 + (s & 127)) * 128 + grp * 2 + (s >> 7);
        *(uint4*)&g_h[tok * 256 + chq + seg * 8] = *(const uint4*)&sO[s * 40 + seg * 8];
    }
}

// ---------------------------------------------------------------------------
// launch
// ---------------------------------------------------------------------------
extern "C" void kernel_launch(void* const* d_in, const int* in_sizes, int n_in,
                              void* d_out, int out_size) {
    const float* x     = (const float*)d_in[0];
    const float* Wqkv  = (const float*)d_in[1];
    const float* bqkv  = (const float*)d_in[2];
    const float* Wproj = (const float*)d_in[3];
    const float* bproj = (const float*)d_in[4];
    const float* gamma = (const float*)d_in[5];
    const float* beta  = (const float*)d_in[6];
    float* out = (float*)d_out;

    cudaFuncSetAttribute(gemm0_persist, cudaFuncAttributeMaxDynamicSharedMemorySize, GEMM0_SMEM);
    cudaFuncSetAttribute(gemm1_persist, cudaFuncAttributeMaxDynamicSharedMemorySize, GEMM1_SMEM);
    cudaFuncSetAttribute(attn_kernel, cudaFuncAttributeMaxDynamicSharedMemorySize, ATTN_SMEM);

    prep_weights<<<768, 256>>>(Wqkv, Wproj);
    gemm0_persist<<<TOKENS / 128, 256, GEMM0_SMEM>>>(x, gamma, beta, bqkv);
    attn_kernel<<<4096, 256, ATTN_SMEM>>>();
    gemm1_persist<<<TOKENS / 128, 256, GEMM1_SMEM>>>(bproj, x, out);
}

// round 9
// speedup vs baseline: 1.0573x; 1.0036x over previous
#include <cuda_runtime.h>
#include <cuda_bf16.h>
#include <cstdint>

#define TOKENS 131072            // 8 * 128 * 128
#define DIM 256

// scale * log2(e) folded into Q at GEMM0 epilogue
#define K2SCALE 0.25503837897544077f

// ---------------------------------------------------------------------------
// Scratch (device globals — no cudaMalloc allowed)
// ---------------------------------------------------------------------------
__device__ __nv_bfloat16 g_qkv[(size_t)TOKENS * 3 * DIM];     // 192 MiB
__device__ __nv_bfloat16 g_h[(size_t)TOKENS * DIM];           //  64 MiB
__device__ __nv_bfloat16 g_WqkvT[3 * DIM * DIM];              // [768][256]
__device__ __nv_bfloat16 g_WprojT[DIM * DIM];                 // [256][256]

// ---------------------------------------------------------------------------
// PTX helpers
// ---------------------------------------------------------------------------
// NON-volatile mma: data deps (fragment inputs, accumulator in/out) fully
// order it; letting the compiler reorder enables software pipelining of
// ldsm(ks+1) above mma(ks) without extra named registers.
__device__ __forceinline__ void mma_bf16(float* c, const uint32_t* a, const uint32_t* b) {
    asm("mma.sync.aligned.m16n8k16.row.col.f32.bf16.bf16.f32 "
        "{%0,%1,%2,%3}, {%4,%5,%6,%7}, {%8,%9}, {%0,%1,%2,%3};\n"
        : "+f"(c[0]), "+f"(c[1]), "+f"(c[2]), "+f"(c[3])
        : "r"(a[0]), "r"(a[1]), "r"(a[2]), "r"(a[3]), "r"(b[0]), "r"(b[1]));
}

// ldsm stays volatile: it reads shared memory that asm constraints don't
// declare, so it must not be moved across barriers.
__device__ __forceinline__ void ldsm_x4(uint32_t* r, uint32_t addr) {
    asm volatile("ldmatrix.sync.aligned.m8n8.x4.shared.b16 {%0,%1,%2,%3}, [%4];"
                 : "=r"(r[0]), "=r"(r[1]), "=r"(r[2]), "=r"(r[3]) : "r"(addr));
}

__device__ __forceinline__ void cp_async16(void* smem_ptr, const void* gmem_ptr) {
    uint32_t s = (uint32_t)__cvta_generic_to_shared(smem_ptr);
    asm volatile("cp.async.cg.shared.global [%0], [%1], 16;\n" :: "r"(s), "l"(gmem_ptr));
}

__device__ __forceinline__ uint32_t pack_bf(float x, float y) {
    __nv_bfloat162 h = __floats2bfloat162_rn(x, y);
    return *reinterpret_cast<uint32_t*>(&h);
}

// force the MUFU fast path regardless of compiler fast-math flags
__device__ __forceinline__ float ex2_fast(float x) {
    float y;
    asm("ex2.approx.f32 %0, %1;" : "=f"(y) : "f"(x));
    return y;
}

// ---------------------------------------------------------------------------
// Weight prep: transpose + convert to bf16 (tiny)
// ---------------------------------------------------------------------------
__global__ void prep_weights(const float* __restrict__ Wqkv, const float* __restrict__ Wproj) {
    int n = blockIdx.x;        // 0..767
    int k = threadIdx.x;       // 0..255
    g_WqkvT[n * DIM + k] = __float2bfloat16(Wqkv[(size_t)k * 768 + n]);
    if (n < DIM)
        g_WprojT[n * DIM + k] = __float2bfloat16(Wproj[(size_t)k * DIM + n]);
}

// ---------------------------------------------------------------------------
// GEMM0 (bf16, persistent over N, LN fused): qkv[M,768] = LN(x)[M,256] x Wqkv
// grid = 1024 M-blocks. LN in the prologue writes the bf16 A tile (128x256,
// stride 264) straight to smem, overlapped with the first B-tile cp.async.
// Then 6 N-tiles x 4 K-blocks, double-buffered B, single barrier/iter.
// Q channels (it 0,1) scaled by K2SCALE.
// smem: A 128x264x2 = 67584 B; B 2 x 128x72x2 = 36864 B; total 104448 B
// ---------------------------------------------------------------------------
#define GEMM0_SMEM 104448

__global__ __launch_bounds__(256, 2) void gemm0_persist(const float* __restrict__ x,
                                                        const float* __restrict__ gamma,
                                                        const float* __restrict__ beta,
                                                        const float* __restrict__ bias) {
    extern __shared__ __nv_bfloat16 sm[];
    // A at elems [0, 33792), B stage s at 33792 + s*9216

    int m0 = blockIdx.x * 128;
    int tid = threadIdx.x;
    int lane = tid & 31, warp = tid >> 5;
    int wm = warp >> 2, wn = warp & 3;   // 2 x 4 warp grid
    int g = lane >> 2, t = lane & 3;

    int arow = lane & 15;
    int acol = (lane >> 4) << 3;
    int brow = (lane & 7) + ((lane >> 4) << 3);
    int bcol = (lane & 8) ? 8 : 0;
    uint32_t smem_u32 = (uint32_t)__cvta_generic_to_shared(sm);
    uint32_t aBase = smem_u32;

    auto load_B = [&](int f, int st) {     // f = flat index -> (it, kb)
        int it = f >> 2, kb = f & 3;
#pragma unroll
        for (int i = 0; i < 4; i++) {
            int li = tid + i * 256;
            int row = li >> 3, seg = li & 7;
            cp_async16(&sm[33792 + st * 9216 + row * 72 + seg * 8],
                       &g_WqkvT[(size_t)(it * 128 + row) * 256 + kb * 64 + seg * 8]);
        }
        asm volatile("cp.async.commit_group;\n" ::: "memory");
    };

    load_B(0, 0);   // overlap first B load with LN prologue

    // ---- LN prologue: 8 warps x 16 rows, write bf16 A tile to smem ----
    {
        int c0 = lane * 8;
        float4 ga = *(const float4*)(gamma + c0);
        float4 gb = *(const float4*)(gamma + c0 + 4);
        float4 ba = *(const float4*)(beta + c0);
        float4 bb = *(const float4*)(beta + c0 + 4);
        float gg[8] = {ga.x, ga.y, ga.z, ga.w, gb.x, gb.y, gb.z, gb.w};
        float be[8] = {ba.x, ba.y, ba.z, ba.w, bb.x, bb.y, bb.z, bb.w};
#pragma unroll 4
        for (int i = 0; i < 16; i++) {
            int row = warp * 16 + i;
            const float* xr = x + (size_t)(m0 + row) * 256 + c0;
            float4 v0 = *(const float4*)xr;
            float4 v1 = *(const float4*)(xr + 4);
            float v[8] = {v0.x, v0.y, v0.z, v0.w, v1.x, v1.y, v1.z, v1.w};
            float s = 0.f, sq = 0.f;
#pragma unroll
            for (int j = 0; j < 8; j++) { s += v[j]; sq += v[j] * v[j]; }
#pragma unroll
            for (int o = 16; o > 0; o >>= 1) {
                s  += __shfl_xor_sync(0xffffffffu, s, o);
                sq += __shfl_xor_sync(0xffffffffu, sq, o);
            }
            float mean = s * (1.0f / DIM);
            float var  = sq * (1.0f / DIM) - mean * mean;
            float rstd = rsqrtf(var + 1e-5f);
            __nv_bfloat16 y[8];
#pragma unroll
            for (int j = 0; j < 8; j++)
                y[j] = __float2bfloat16((v[j] - mean) * rstd * gg[j] + be[j]);
            *(uint4*)&sm[row * 264 + c0] = *(uint4*)y;
        }
    }

    float acc[4][4][4];
#pragma unroll
    for (int i = 0; i < 4; i++)
#pragma unroll
        for (int j = 0; j < 4; j++)
#pragma unroll
            for (int k = 0; k < 4; k++) acc[i][j][k] = 0.f;

    for (int f = 0; f < 24; f++) {
        int it = f >> 2, kb = f & 3, st = f & 1;
        asm volatile("cp.async.wait_group 0;\n" ::: "memory");
        __syncthreads();
        if (f + 1 < 24) load_B(f + 1, (f + 1) & 1);

        uint32_t bBase = smem_u32 + (33792 + st * 9216) * 2;

#pragma unroll
        for (int ks = 0; ks < 4; ks++) {
            int kk = kb * 64 + ks * 16;
            uint32_t af[4][4], bfr[4][2];
#pragma unroll
            for (int mt = 0; mt < 4; mt++)
                ldsm_x4(af[mt], aBase + ((wm * 64 + mt * 16 + arow) * 264 + kk + acol) * 2);
#pragma unroll
            for (int p = 0; p < 2; p++) {
                uint32_t r4[4];
                ldsm_x4(r4, bBase + ((wn * 32 + p * 16 + brow) * 72 + ks * 16 + bcol) * 2);
                bfr[2 * p][0] = r4[0]; bfr[2 * p][1] = r4[1];
                bfr[2 * p + 1][0] = r4[2]; bfr[2 * p + 1][1] = r4[3];
            }
#pragma unroll
            for (int mt = 0; mt < 4; mt++)
#pragma unroll
                for (int nt = 0; nt < 4; nt++)
                    mma_bf16(acc[mt][nt], af[mt], bfr[nt]);
        }

        if (kb == 3) {
            int n0 = it * 128;
            float sc = (it < 2) ? K2SCALE : 1.0f;   // Q scaled; K, V plain
#pragma unroll
            for (int mt = 0; mt < 4; mt++) {
                int r = m0 + wm * 64 + mt * 16 + g;
#pragma unroll
                for (int nt = 0; nt < 4; nt++) {
                    int c = n0 + wn * 32 + nt * 8 + t * 2;
                    float b0 = bias[c], b1 = bias[c + 1];
                    *reinterpret_cast<__nv_bfloat162*>(&g_qkv[(size_t)r * 768 + c]) =
                        __floats2bfloat162_rn((acc[mt][nt][0] + b0) * sc,
                                              (acc[mt][nt][1] + b1) * sc);
                    *reinterpret_cast<__nv_bfloat162*>(&g_qkv[(size_t)(r + 8) * 768 + c]) =
                        __floats2bfloat162_rn((acc[mt][nt][2] + b0) * sc,
                                              (acc[mt][nt][3] + b1) * sc);
#pragma unroll
                    for (int k = 0; k < 4; k++) acc[mt][nt][k] = 0.f;
                }
            }
        }
    }
}

// ---------------------------------------------------------------------------
// GEMM1 (bf16, persistent over N): out[M,256] = h[M,256] x Wproj + bproj + x
// Same single-barrier pipeline; 2 N-tiles x 4 K-blocks. fp32 out + residual.
// ---------------------------------------------------------------------------
#define GEMM1_SMEM 104448

__global__ __launch_bounds__(256, 2) void gemm1_persist(const float* __restrict__ bias,
                                                        const float* __restrict__ resid,
                                                        float* __restrict__ outf) {
    extern __shared__ __nv_bfloat16 sm[];

    int m0 = blockIdx.x * 128;
    int tid = threadIdx.x;
    int lane = tid & 31, warp = tid >> 5;
    int wm = warp >> 2, wn = warp & 3;
    int g = lane >> 2, t = lane & 3;

    int arow = lane & 15;
    int acol = (lane >> 4) << 3;
    int brow = (lane & 7) + ((lane >> 4) << 3);
    int bcol = (lane & 8) ? 8 : 0;
    uint32_t smem_u32 = (uint32_t)__cvta_generic_to_shared(sm);
    uint32_t aBase = smem_u32;

    auto load_B = [&](int f, int st) {
        int it = f >> 2, kb = f & 3;
#pragma unroll
        for (int i = 0; i < 4; i++) {
            int li = tid + i * 256;
            int row = li >> 3, seg = li & 7;
            cp_async16(&sm[33792 + st * 9216 + row * 72 + seg * 8],
                       &g_WprojT[(size_t)(it * 128 + row) * 256 + kb * 64 + seg * 8]);
        }
        asm volatile("cp.async.commit_group;\n" ::: "memory");
    };

    load_B(0, 0);

    // ---- load A (once): 128 x 256 bf16, stride 264 ----
#pragma unroll
    for (int i = 0; i < 16; i++) {
        int li = tid + i * 256;
        int row = li >> 5, seg = li & 31;
        cp_async16(&sm[row * 264 + seg * 8],
                   &g_h[(size_t)(m0 + row) * 256 + seg * 8]);
    }
    asm volatile("cp.async.commit_group;\n" ::: "memory");

    float acc[4][4][4];
#pragma unroll
    for (int i = 0; i < 4; i++)
#pragma unroll
        for (int j = 0; j < 4; j++)
#pragma unroll
            for (int k = 0; k < 4; k++) acc[i][j][k] = 0.f;

    for (int f = 0; f < 8; f++) {
        int it = f >> 2, kb = f & 3, st = f & 1;
        asm volatile("cp.async.wait_group 0;\n" ::: "memory");
        __syncthreads();
        if (f + 1 < 8) load_B(f + 1, (f + 1) & 1);

        uint32_t bBase = smem_u32 + (33792 + st * 9216) * 2;

#pragma unroll
        for (int ks = 0; ks < 4; ks++) {
            int kk = kb * 64 + ks * 16;
            uint32_t af[4][4], bfr[4][2];
#pragma unroll
            for (int mt = 0; mt < 4; mt++)
                ldsm_x4(af[mt], aBase + ((wm * 64 + mt * 16 + arow) * 264 + kk + acol) * 2);
#pragma unroll
            for (int p = 0; p < 2; p++) {
                uint32_t r4[4];
                ldsm_x4(r4, bBase + ((wn * 32 + p * 16 + brow) * 72 + ks * 16 + bcol) * 2);
                bfr[2 * p][0] = r4[0]; bfr[2 * p][1] = r4[1];
                bfr[2 * p + 1][0] = r4[2]; bfr[2 * p + 1][1] = r4[3];
            }
#pragma unroll
            for (int mt = 0; mt < 4; mt++)
#pragma unroll
                for (int nt = 0; nt < 4; nt++)
                    mma_bf16(acc[mt][nt], af[mt], bfr[nt]);
        }

        if (kb == 3) {
            int n0 = it * 128;
#pragma unroll
            for (int mt = 0; mt < 4; mt++) {
                int r = m0 + wm * 64 + mt * 16 + g;
#pragma unroll
                for (int nt = 0; nt < 4; nt++) {
                    int c = n0 + wn * 32 + nt * 8 + t * 2;
                    float b0 = bias[c], b1 = bias[c + 1];
                    size_t i0 = (size_t)r * 256 + c;
                    float2 rx0 = *(const float2*)(resid + i0);
                    float2 o0;
                    o0.x = acc[mt][nt][0] + b0 + rx0.x;
                    o0.y = acc[mt][nt][1] + b1 + rx0.y;
                    *(float2*)(outf + i0) = o0;
                    size_t i1 = (size_t)(r + 8) * 256 + c;
                    float2 rx1 = *(const float2*)(resid + i1);
                    float2 o1;
                    o1.x = acc[mt][nt][2] + b0 + rx1.x;
                    o1.y = acc[mt][nt][3] + b1 + rx1.y;
                    *(float2*)(outf + i1) = o1;
#pragma unroll
                    for (int k = 0; k < 4; k++) acc[mt][nt][k] = 0.f;
                }
            }
        }
    }
}

// ---------------------------------------------------------------------------
// Stripe attention (round-4 structure, non-volatile mma).
// One block = (branch, batch, stripe-group, head). seq 256, head_dim 32.
// 8 warps x 32 q-rows. No-max softmax; scale*log2e pre-folded into Q.
// smem: sQ [256][40] (reused as sO), sK [256][40], sVt [32][264] = 57856 B
// ---------------------------------------------------------------------------
#define ATTN_SMEM 57856

__global__ __launch_bounds__(256, 2) void attn_kernel() {
    extern __shared__ __nv_bfloat16 smA[];
    __nv_bfloat16* sQ  = smA;                    // [256][40]  (reused as sO)
    __nv_bfloat16* sK  = smA + 10240;            // [256][40]
    __nv_bfloat16* sVt = smA + 20480;            // [32][264]  (V transposed)
    __nv_bfloat16* sO  = sQ;

    int bid = blockIdx.x;
    int head   = bid & 3;
    int grp    = (bid >> 2) & 63;
    int b      = (bid >> 8) & 7;
    int branch = bid >> 11;                       // 0 = horizontal, 1 = vertical
    int off = branch << 7;                        // 0 or 128
    int chq = off + head * 32;

    int tid = threadIdx.x;
    int lane = tid & 31, warp = tid >> 5;

    // --- load Q, K, V(transposed) for this (group, head) ---
    {
        int s = tid;  // seq position 0..255
        size_t tok;
        if (branch == 0)
            tok = (size_t)(b * 128 + grp * 2) * 128 + s;
        else
            tok = (size_t)(b * 128 + (s & 127)) * 128 + grp * 2 + (s >> 7);
        const __nv_bfloat16* base = g_qkv + tok * 768;
#pragma unroll
        for (int i = 0; i < 4; i++)
            *(uint4*)&sQ[s * 40 + i * 8] = *(const uint4*)&base[chq + i * 8];
#pragma unroll
        for (int i = 0; i < 4; i++)
            *(uint4*)&sK[s * 40 + i * 8] = *(const uint4*)&base[256 + chq + i * 8];
        __nv_bfloat16 vv[32];
#pragma unroll
        for (int i = 0; i < 4; i++)
            *(uint4*)&vv[i * 8] = *(const uint4*)&base[512 + chq + i * 8];
#pragma unroll
        for (int d = 0; d < 32; d++)
            sVt[d * 264 + s] = vv[d];
    }
    __syncthreads();

    int g = lane >> 2, t = lane & 3;
    int mbase = warp * 32;

    int arow = lane & 15;
    int acol = (lane >> 4) << 3;
    int brow = (lane & 7) + ((lane >> 4) << 3);
    int bcol = (lane & 8) ? 8 : 0;
    uint32_t qBase = (uint32_t)__cvta_generic_to_shared(sQ);
    uint32_t kBase = (uint32_t)__cvta_generic_to_shared(sK);
    uint32_t vBase = (uint32_t)__cvta_generic_to_shared(sVt);

    // persistent Q fragments (warp's 32 rows x k=32)
    uint32_t qa[2][2][4];
#pragma unroll
    for (int mt = 0; mt < 2; mt++)
#pragma unroll
        for (int ks = 0; ks < 2; ks++)
            ldsm_x4(qa[mt][ks],
                    qBase + ((mbase + mt * 16 + arow) * 40 + ks * 16 + acol) * 2);

    float o[2][4][4];
#pragma unroll
    for (int i = 0; i < 2; i++)
#pragma unroll
        for (int j = 0; j < 4; j++)
#pragma unroll
            for (int k = 0; k < 4; k++) o[i][j][k] = 0.f;
    float lrow[2][2] = {{0.f, 0.f}, {0.f, 0.f}};

#pragma unroll
    for (int kc = 0; kc < 8; kc++) {
        float sacc[2][4][4];
#pragma unroll
        for (int i = 0; i < 2; i++)
#pragma unroll
            for (int j = 0; j < 4; j++)
#pragma unroll
                for (int k = 0; k < 4; k++) sacc[i][j][k] = 0.f;

#pragma unroll
        for (int ks = 0; ks < 2; ks++) {
            uint32_t kb[4][2];
#pragma unroll
            for (int p = 0; p < 2; p++) {
                uint32_t r4[4];
                ldsm_x4(r4, kBase + ((kc * 32 + p * 16 + brow) * 40 + ks * 16 + bcol) * 2);
                kb[2 * p][0] = r4[0]; kb[2 * p][1] = r4[1];
                kb[2 * p + 1][0] = r4[2]; kb[2 * p + 1][1] = r4[3];
            }
#pragma unroll
            for (int mt = 0; mt < 2; mt++)
#pragma unroll
                for (int nt = 0; nt < 4; nt++)
                    mma_bf16(sacc[mt][nt], qa[mt][ks], kb[nt]);
        }

        // P = exp2(S) via MUFU
#pragma unroll
        for (int mt = 0; mt < 2; mt++)
#pragma unroll
            for (int hi = 0; hi < 2; hi++) {
                float rs = 0.f;
#pragma unroll
                for (int nt = 0; nt < 4; nt++) {
                    float p0 = ex2_fast(sacc[mt][nt][hi * 2]);
                    float p1 = ex2_fast(sacc[mt][nt][hi * 2 + 1]);
                    sacc[mt][nt][hi * 2] = p0;
                    sacc[mt][nt][hi * 2 + 1] = p1;
                    rs += p0 + p1;
                }
                lrow[mt][hi] += rs;
            }

        // O += P V
#pragma unroll
        for (int ksv = 0; ksv < 2; ksv++) {
            uint32_t pa[2][4];
#pragma unroll
            for (int mt = 0; mt < 2; mt++) {
                pa[mt][0] = pack_bf(sacc[mt][2 * ksv][0], sacc[mt][2 * ksv][1]);
                pa[mt][1] = pack_bf(sacc[mt][2 * ksv][2], sacc[mt][2 * ksv][3]);
                pa[mt][2] = pack_bf(sacc[mt][2 * ksv + 1][0], sacc[mt][2 * ksv + 1][1]);
                pa[mt][3] = pack_bf(sacc[mt][2 * ksv + 1][2], sacc[mt][2 * ksv + 1][3]);
            }
            uint32_t vb[4][2];
            int kkv = kc * 32 + ksv * 16;
#pragma unroll
            for (int p = 0; p < 2; p++) {
                uint32_t r4[4];
                ldsm_x4(r4, vBase + ((p * 16 + brow) * 264 + kkv + bcol) * 2);
                vb[2 * p][0] = r4[0]; vb[2 * p][1] = r4[1];
                vb[2 * p + 1][0] = r4[2]; vb[2 * p + 1][1] = r4[3];
            }
#pragma unroll
            for (int mt = 0; mt < 2; mt++)
#pragma unroll
                for (int nt = 0; nt < 4; nt++)
                    mma_bf16(o[mt][nt], pa[mt], vb[nt]);
        }
    }

    // final row-sum reduce, normalize, stage to smem (bf16)
#pragma unroll
    for (int mt = 0; mt < 2; mt++)
#pragma unroll
        for (int hi = 0; hi < 2; hi++) {
            float l = lrow[mt][hi];
            l += __shfl_xor_sync(0xffffffffu, l, 1);
            l += __shfl_xor_sync(0xffffffffu, l, 2);
            float inv = 1.0f / l;
            int r = mbase + mt * 16 + g + hi * 8;
#pragma unroll
            for (int nt = 0; nt < 4; nt++) {
                *reinterpret_cast<__nv_bfloat162*>(&sO[r * 40 + nt * 8 + t * 2]) =
                    __floats2bfloat162_rn(o[mt][nt][hi * 2] * inv, o[mt][nt][hi * 2 + 1] * inv);
            }
        }
    __syncthreads();

    // cooperative coalesced write to g_h
#pragma unroll
    for (int i = 0; i < 4; i++) {
        int li = i * 256 + tid;
        int s = li >> 2, seg = li & 3;
        size_t tok;
        if (branch == 0)
            tok = (size_t)(b * 128 + grp * 2) * 128 + s;
        else
            tok = (size_t)(b * 128 + (s & 127)) * 128 + grp * 2 + (s >> 7);
        *(uint4*)&g_h[tok * 256 + chq + seg * 8] = *(const uint4*)&sO[s * 40 + seg * 8];
    }
}

// ---------------------------------------------------------------------------
// launch
// ---------------------------------------------------------------------------
extern "C" void kernel_launch(void* const* d_in, const int* in_sizes, int n_in,
                              void* d_out, int out_size) {
    const float* x     = (const float*)d_in[0];
    const float* Wqkv  = (const float*)d_in[1];
    const float* bqkv  = (const float*)d_in[2];
    const float* Wproj = (const float*)d_in[3];
    const float* bproj = (const float*)d_in[4];
    const float* gamma = (const float*)d_in[5];
    const float* beta  = (const float*)d_in[6];
    float* out = (float*)d_out;

    cudaFuncSetAttribute(gemm0_persist, cudaFuncAttributeMaxDynamicSharedMemorySize, GEMM0_SMEM);
    cudaFuncSetAttribute(gemm1_persist, cudaFuncAttributeMaxDynamicSharedMemorySize, GEMM1_SMEM);
    cudaFuncSetAttribute(attn_kernel, cudaFuncAttributeMaxDynamicSharedMemorySize, ATTN_SMEM);

    prep_weights<<<768, 256>>>(Wqkv, Wproj);
    gemm0_persist<<<TOKENS / 128, 256, GEMM0_SMEM>>>(x, gamma, beta, bqkv);
    attn_kernel<<<4096, 256, ATTN_SMEM>>>();
    gemm1_persist<<<TOKENS / 128, 256, GEMM1_SMEM>>>(bproj, x, out);
}

// round 10
// speedup vs baseline: 1.0818x; 1.0232x over previous
#include <cuda_runtime.h>
#include <cuda_bf16.h>
#include <cstdint>

#define TOKENS 131072            // 8 * 128 * 128
#define DIM 256

// scale * log2(e) folded into Q at GEMM0 epilogue
#define K2SCALE 0.25503837897544077f

// ---------------------------------------------------------------------------
// Scratch (device globals — no cudaMalloc allowed)
// ---------------------------------------------------------------------------
__device__ __nv_bfloat16 g_qkv[(size_t)TOKENS * 3 * DIM];     // 192 MiB
__device__ __nv_bfloat16 g_h[(size_t)TOKENS * DIM];           //  64 MiB
__device__ __nv_bfloat16 g_WqkvT[3 * DIM * DIM];              // [768][256]
__device__ __nv_bfloat16 g_WprojT[DIM * DIM];                 // [256][256]

// ---------------------------------------------------------------------------
// PTX helpers
// ---------------------------------------------------------------------------
__device__ __forceinline__ void mma_bf16(float* c, const uint32_t* a, const uint32_t* b) {
    asm("mma.sync.aligned.m16n8k16.row.col.f32.bf16.bf16.f32 "
        "{%0,%1,%2,%3}, {%4,%5,%6,%7}, {%8,%9}, {%0,%1,%2,%3};\n"
        : "+f"(c[0]), "+f"(c[1]), "+f"(c[2]), "+f"(c[3])
        : "r"(a[0]), "r"(a[1]), "r"(a[2]), "r"(a[3]), "r"(b[0]), "r"(b[1]));
}

__device__ __forceinline__ void ldsm_x4(uint32_t* r, uint32_t addr) {
    asm volatile("ldmatrix.sync.aligned.m8n8.x4.shared.b16 {%0,%1,%2,%3}, [%4];"
                 : "=r"(r[0]), "=r"(r[1]), "=r"(r[2]), "=r"(r[3]) : "r"(addr));
}

__device__ __forceinline__ void cp_async16(void* smem_ptr, const void* gmem_ptr) {
    uint32_t s = (uint32_t)__cvta_generic_to_shared(smem_ptr);
    asm volatile("cp.async.cg.shared.global [%0], [%1], 16;\n" :: "r"(s), "l"(gmem_ptr));
}

__device__ __forceinline__ uint32_t pack_bf(float x, float y) {
    __nv_bfloat162 h = __floats2bfloat162_rn(x, y);
    return *reinterpret_cast<uint32_t*>(&h);
}

__device__ __forceinline__ float ex2_fast(float x) {
    float y;
    asm("ex2.approx.f32 %0, %1;" : "=f"(y) : "f"(x));
    return y;
}

// swizzled chunk offsets (16B units). A rows = 512B (32 chunks); B rows = 128B (8 chunks).
__device__ __forceinline__ uint32_t a_sw(int row, int c16) {   // bytes
    return (uint32_t)(row * 512 + ((c16 ^ (row & 7)) << 4));
}
__device__ __forceinline__ uint32_t b_sw(int row, int c16) {   // bytes
    return (uint32_t)(row * 128 + ((c16 ^ (row & 7)) << 4));
}

// ---------------------------------------------------------------------------
// Weight prep: transpose + convert to bf16 (tiny)
// ---------------------------------------------------------------------------
__global__ void prep_weights(const float* __restrict__ Wqkv, const float* __restrict__ Wproj) {
    int n = blockIdx.x;        // 0..767
    int k = threadIdx.x;       // 0..255
    g_WqkvT[n * DIM + k] = __float2bfloat16(Wqkv[(size_t)k * 768 + n]);
    if (n < DIM)
        g_WprojT[n * DIM + k] = __float2bfloat16(Wproj[(size_t)k * DIM + n]);
}

// ---------------------------------------------------------------------------
// GEMM0 (bf16, persistent over N, LN fused, 3-stage B pipeline):
// qkv[M,768] = LN(x)[M,256] x Wqkv (+bqkv).
// A: 128x256 bf16, swizzled 512B rows (65536 B), written by LN prologue.
// B: 3 stages x 128x64 bf16 swizzled 128B rows (16384 B each).
// 6 N-tiles x 4 K-blocks; wait_group 1 -> barrier -> issue load(f+2).
// Q channels (it 0,1) scaled by K2SCALE.
// smem total: 65536 + 49152 = 114688 B  (2 CTAs/SM)
// ---------------------------------------------------------------------------
#define GEMM0_SMEM 114688

__global__ __launch_bounds__(256, 2) void gemm0_persist(const float* __restrict__ x,
                                                        const float* __restrict__ gamma,
                                                        const float* __restrict__ beta,
                                                        const float* __restrict__ bias) {
    extern __shared__ char smraw[];
    __nv_bfloat16* smA = (__nv_bfloat16*)smraw;            // A: [0, 65536) bytes
    char* smB = smraw + 65536;                             // B stage s at s*16384

    int m0 = blockIdx.x * 128;
    int tid = threadIdx.x;
    int lane = tid & 31, warp = tid >> 5;
    int wm = warp >> 2, wn = warp & 3;   // 2 x 4 warp grid
    int g = lane >> 2, t = lane & 3;

    int arow = lane & 15;
    int acol = (lane >> 4) << 3;
    int brow = (lane & 7) + ((lane >> 4) << 3);
    int bcol = (lane & 8) ? 8 : 0;
    uint32_t aBase = (uint32_t)__cvta_generic_to_shared(smraw);
    uint32_t bBase0 = aBase + 65536;

    auto load_B = [&](int f, int st) {     // f -> (it, kb)
        int it = f >> 2, kb = f & 3;
#pragma unroll
        for (int i = 0; i < 4; i++) {
            int li = tid + i * 256;           // 0..1023
            int row = li >> 3, c16 = li & 7;  // 128 rows x 8 chunks
            cp_async16(smB + st * 16384 + b_sw(row, c16),
                       &g_WqkvT[(size_t)(it * 128 + row) * 256 + kb * 64 + c16 * 8]);
        }
        asm volatile("cp.async.commit_group;\n" ::: "memory");
    };

    load_B(0, 0);
    load_B(1, 1);

    // ---- LN prologue: 8 warps x 16 rows, write swizzled bf16 A tile ----
    {
        int c0 = lane * 8;                   // chunk index = lane
        float4 ga = *(const float4*)(gamma + c0);
        float4 gb = *(const float4*)(gamma + c0 + 4);
        float4 ba = *(const float4*)(beta + c0);
        float4 bb = *(const float4*)(beta + c0 + 4);
        float gg[8] = {ga.x, ga.y, ga.z, ga.w, gb.x, gb.y, gb.z, gb.w};
        float be[8] = {ba.x, ba.y, ba.z, ba.w, bb.x, bb.y, bb.z, bb.w};
#pragma unroll 4
        for (int i = 0; i < 16; i++) {
            int row = warp * 16 + i;
            const float* xr = x + (size_t)(m0 + row) * 256 + c0;
            float4 v0 = *(const float4*)xr;
            float4 v1 = *(const float4*)(xr + 4);
            float v[8] = {v0.x, v0.y, v0.z, v0.w, v1.x, v1.y, v1.z, v1.w};
            float s = 0.f, sq = 0.f;
#pragma unroll
            for (int j = 0; j < 8; j++) { s += v[j]; sq += v[j] * v[j]; }
#pragma unroll
            for (int o = 16; o > 0; o >>= 1) {
                s  += __shfl_xor_sync(0xffffffffu, s, o);
                sq += __shfl_xor_sync(0xffffffffu, sq, o);
            }
            float mean = s * (1.0f / DIM);
            float var  = sq * (1.0f / DIM) - mean * mean;
            float rstd = rsqrtf(var + 1e-5f);
            __nv_bfloat16 y[8];
#pragma unroll
            for (int j = 0; j < 8; j++)
                y[j] = __float2bfloat16((v[j] - mean) * rstd * gg[j] + be[j]);
            *(uint4*)((char*)smA + a_sw(row, lane)) = *(uint4*)y;
        }
    }

    float acc[4][4][4];
#pragma unroll
    for (int i = 0; i < 4; i++)
#pragma unroll
        for (int j = 0; j < 4; j++)
#pragma unroll
            for (int k = 0; k < 4; k++) acc[i][j][k] = 0.f;

    for (int f = 0; f < 24; f++) {
        int it = f >> 2, kb = f & 3;
        int st = f % 3;
        asm volatile("cp.async.wait_group 1;\n" ::: "memory");
        __syncthreads();
        if (f + 2 < 24) load_B(f + 2, (f + 2) % 3);

        uint32_t bB = bBase0 + st * 16384;

#pragma unroll
        for (int ks = 0; ks < 4; ks++) {
            int c16a = (kb * 64 + ks * 16 + acol) >> 3;
            int c16b = (ks * 16 + bcol) >> 3;
            uint32_t af[4][4], bfr[4][2];
#pragma unroll
            for (int mt = 0; mt < 4; mt++) {
                int r = wm * 64 + mt * 16 + arow;
                ldsm_x4(af[mt], aBase + a_sw(r, c16a));
            }
#pragma unroll
            for (int p = 0; p < 2; p++) {
                int r = wn * 32 + p * 16 + brow;
                uint32_t r4[4];
                ldsm_x4(r4, bB + b_sw(r, c16b));
                bfr[2 * p][0] = r4[0]; bfr[2 * p][1] = r4[1];
                bfr[2 * p + 1][0] = r4[2]; bfr[2 * p + 1][1] = r4[3];
            }
#pragma unroll
            for (int mt = 0; mt < 4; mt++)
#pragma unroll
                for (int nt = 0; nt < 4; nt++)
                    mma_bf16(acc[mt][nt], af[mt], bfr[nt]);
        }

        if (kb == 3) {
            int n0 = it * 128;
            float sc = (it < 2) ? K2SCALE : 1.0f;   // Q scaled; K, V plain
#pragma unroll
            for (int mt = 0; mt < 4; mt++) {
                int r = m0 + wm * 64 + mt * 16 + g;
#pragma unroll
                for (int nt = 0; nt < 4; nt++) {
                    int c = n0 + wn * 32 + nt * 8 + t * 2;
                    float b0 = bias[c], b1 = bias[c + 1];
                    *reinterpret_cast<__nv_bfloat162*>(&g_qkv[(size_t)r * 768 + c]) =
                        __floats2bfloat162_rn((acc[mt][nt][0] + b0) * sc,
                                              (acc[mt][nt][1] + b1) * sc);
                    *reinterpret_cast<__nv_bfloat162*>(&g_qkv[(size_t)(r + 8) * 768 + c]) =
                        __floats2bfloat162_rn((acc[mt][nt][2] + b0) * sc,
                                              (acc[mt][nt][3] + b1) * sc);
#pragma unroll
                    for (int k = 0; k < 4; k++) acc[mt][nt][k] = 0.f;
                }
            }
        }
    }
}

// ---------------------------------------------------------------------------
// GEMM1 (bf16, persistent over N, 3-stage B pipeline):
// out[M,256] = h[M,256] x Wproj + bproj + x  (fp32 out)
// smem: A 65536 (swizzled, cp.async) + 3 x 16384 B = 114688 B
// ---------------------------------------------------------------------------
#define GEMM1_SMEM 114688

__global__ __launch_bounds__(256, 2) void gemm1_persist(const float* __restrict__ bias,
                                                        const float* __restrict__ resid,
                                                        float* __restrict__ outf) {
    extern __shared__ char smraw[];
    char* smB = smraw + 65536;

    int m0 = blockIdx.x * 128;
    int tid = threadIdx.x;
    int lane = tid & 31, warp = tid >> 5;
    int wm = warp >> 2, wn = warp & 3;
    int g = lane >> 2, t = lane & 3;

    int arow = lane & 15;
    int acol = (lane >> 4) << 3;
    int brow = (lane & 7) + ((lane >> 4) << 3);
    int bcol = (lane & 8) ? 8 : 0;
    uint32_t aBase = (uint32_t)__cvta_generic_to_shared(smraw);
    uint32_t bBase0 = aBase + 65536;

    auto load_B = [&](int f, int st) {
        int it = f >> 2, kb = f & 3;
#pragma unroll
        for (int i = 0; i < 4; i++) {
            int li = tid + i * 256;
            int row = li >> 3, c16 = li & 7;
            cp_async16(smB + st * 16384 + b_sw(row, c16),
                       &g_WprojT[(size_t)(it * 128 + row) * 256 + kb * 64 + c16 * 8]);
        }
        asm volatile("cp.async.commit_group;\n" ::: "memory");
    };

    load_B(0, 0);

    // ---- load A (once): 128 x 256 bf16, swizzled rows ----
#pragma unroll
    for (int i = 0; i < 16; i++) {
        int li = tid + i * 256;
        int row = li >> 5, c16 = li & 31;
        cp_async16(smraw + a_sw(row, c16),
                   &g_h[(size_t)(m0 + row) * 256 + c16 * 8]);
    }
    asm volatile("cp.async.commit_group;\n" ::: "memory");

    load_B(1, 1);

    float acc[4][4][4];
#pragma unroll
    for (int i = 0; i < 4; i++)
#pragma unroll
        for (int j = 0; j < 4; j++)
#pragma unroll
            for (int k = 0; k < 4; k++) acc[i][j][k] = 0.f;

    for (int f = 0; f < 8; f++) {
        int it = f >> 2, kb = f & 3;
        int st = f % 3;
        asm volatile("cp.async.wait_group 1;\n" ::: "memory");
        __syncthreads();
        if (f + 2 < 8) load_B(f + 2, (f + 2) % 3);

        uint32_t bB = bBase0 + st * 16384;

#pragma unroll
        for (int ks = 0; ks < 4; ks++) {
            int c16a = (kb * 64 + ks * 16 + acol) >> 3;
            int c16b = (ks * 16 + bcol) >> 3;
            uint32_t af[4][4], bfr[4][2];
#pragma unroll
            for (int mt = 0; mt < 4; mt++) {
                int r = wm * 64 + mt * 16 + arow;
                ldsm_x4(af[mt], aBase + a_sw(r, c16a));
            }
#pragma unroll
            for (int p = 0; p < 2; p++) {
                int r = wn * 32 + p * 16 + brow;
                uint32_t r4[4];
                ldsm_x4(r4, bB + b_sw(r, c16b));
                bfr[2 * p][0] = r4[0]; bfr[2 * p][1] = r4[1];
                bfr[2 * p + 1][0] = r4[2]; bfr[2 * p + 1][1] = r4[3];
            }
#pragma unroll
            for (int mt = 0; mt < 4; mt++)
#pragma unroll
                for (int nt = 0; nt < 4; nt++)
                    mma_bf16(acc[mt][nt], af[mt], bfr[nt]);
        }

        if (kb == 3) {
            int n0 = it * 128;
#pragma unroll
            for (int mt = 0; mt < 4; mt++) {
                int r = m0 + wm * 64 + mt * 16 + g;
#pragma unroll
                for (int nt = 0; nt < 4; nt++) {
                    int c = n0 + wn * 32 + nt * 8 + t * 2;
                    float b0 = bias[c], b1 = bias[c + 1];
                    size_t i0 = (size_t)r * 256 + c;
                    float2 rx0 = *(const float2*)(resid + i0);
                    float2 o0;
                    o0.x = acc[mt][nt][0] + b0 + rx0.x;
                    o0.y = acc[mt][nt][1] + b1 + rx0.y;
                    *(float2*)(outf + i0) = o0;
                    size_t i1 = (size_t)(r + 8) * 256 + c;
                    float2 rx1 = *(const float2*)(resid + i1);
                    float2 o1;
                    o1.x = acc[mt][nt][2] + b0 + rx1.x;
                    o1.y = acc[mt][nt][3] + b1 + rx1.y;
                    *(float2*)(outf + i1) = o1;
#pragma unroll
                    for (int k = 0; k < 4; k++) acc[mt][nt][k] = 0.f;
                }
            }
        }
    }
}

// ---------------------------------------------------------------------------
// Stripe attention (round-4 measured-best). One block = (branch, batch,
// stripe-group, head). seq 256, head_dim 32. 8 warps x 32 q-rows.
// No-max softmax; scale*log2e pre-folded into Q.
// smem: sQ [256][40] (reused as sO), sK [256][40], sVt [32][264] = 57856 B
// ---------------------------------------------------------------------------
#define ATTN_SMEM 57856

__global__ __launch_bounds__(256, 2) void attn_kernel() {
    extern __shared__ __nv_bfloat16 smA[];
    __nv_bfloat16* sQ  = smA;                    // [256][40]  (reused as sO)
    __nv_bfloat16* sK  = smA + 10240;            // [256][40]
    __nv_bfloat16* sVt = smA + 20480;            // [32][264]  (V transposed)
    __nv_bfloat16* sO  = sQ;

    int bid = blockIdx.x;
    int head   = bid & 3;
    int grp    = (bid >> 2) & 63;
    int b      = (bid >> 8) & 7;
    int branch = bid >> 11;                       // 0 = horizontal, 1 = vertical
    int off = branch << 7;                        // 0 or 128
    int chq = off + head * 32;

    int tid = threadIdx.x;
    int lane = tid & 31, warp = tid >> 5;

    {
        int s = tid;  // seq position 0..255
        size_t tok;
        if (branch == 0)
            tok = (size_t)(b * 128 + grp * 2) * 128 + s;
        else
            tok = (size_t)(b * 128 + (s & 127)) * 128 + grp * 2 + (s >> 7);
        const __nv_bfloat16* base = g_qkv + tok * 768;
#pragma unroll
        for (int i = 0; i < 4; i++)
            *(uint4*)&sQ[s * 40 + i * 8] = *(const uint4*)&base[chq + i * 8];
#pragma unroll
        for (int i = 0; i < 4; i++)
            *(uint4*)&sK[s * 40 + i * 8] = *(const uint4*)&base[256 + chq + i * 8];
        __nv_bfloat16 vv[32];
#pragma unroll
        for (int i = 0; i < 4; i++)
            *(uint4*)&vv[i * 8] = *(const uint4*)&base[512 + chq + i * 8];
#pragma unroll
        for (int d = 0; d < 32; d++)
            sVt[d * 264 + s] = vv[d];
    }
    __syncthreads();

    int g = lane >> 2, t = lane & 3;
    int mbase = warp * 32;

    int arow = lane & 15;
    int acol = (lane >> 4) << 3;
    int brow = (lane & 7) + ((lane >> 4) << 3);
    int bcol = (lane & 8) ? 8 : 0;
    uint32_t qBase = (uint32_t)__cvta_generic_to_shared(sQ);
    uint32_t kBase = (uint32_t)__cvta_generic_to_shared(sK);
    uint32_t vBase = (uint32_t)__cvta_generic_to_shared(sVt);

    uint32_t qa[2][2][4];
#pragma unroll
    for (int mt = 0; mt < 2; mt++)
#pragma unroll
        for (int ks = 0; ks < 2; ks++)
            ldsm_x4(qa[mt][ks],
                    qBase + ((mbase + mt * 16 + arow) * 40 + ks * 16 + acol) * 2);

    float o[2][4][4];
#pragma unroll
    for (int i = 0; i < 2; i++)
#pragma unroll
        for (int j = 0; j < 4; j++)
#pragma unroll
            for (int k = 0; k < 4; k++) o[i][j][k] = 0.f;
    float lrow[2][2] = {{0.f, 0.f}, {0.f, 0.f}};

#pragma unroll
    for (int kc = 0; kc < 8; kc++) {
        float sacc[2][4][4];
#pragma unroll
        for (int i = 0; i < 2; i++)
#pragma unroll
            for (int j = 0; j < 4; j++)
#pragma unroll
                for (int k = 0; k < 4; k++) sacc[i][j][k] = 0.f;

#pragma unroll
        for (int ks = 0; ks < 2; ks++) {
            uint32_t kb[4][2];
#pragma unroll
            for (int p = 0; p < 2; p++) {
                uint32_t r4[4];
                ldsm_x4(r4, kBase + ((kc * 32 + p * 16 + brow) * 40 + ks * 16 + bcol) * 2);
                kb[2 * p][0] = r4[0]; kb[2 * p][1] = r4[1];
                kb[2 * p + 1][0] = r4[2]; kb[2 * p + 1][1] = r4[3];
            }
#pragma unroll
            for (int mt = 0; mt < 2; mt++)
#pragma unroll
                for (int nt = 0; nt < 4; nt++)
                    mma_bf16(sacc[mt][nt], qa[mt][ks], kb[nt]);
        }

        // P = exp2(S) via MUFU
#pragma unroll
        for (int mt = 0; mt < 2; mt++)
#pragma unroll
            for (int hi = 0; hi < 2; hi++) {
                float rs = 0.f;
#pragma unroll
                for (int nt = 0; nt < 4; nt++) {
                    float p0 = ex2_fast(sacc[mt][nt][hi * 2]);
                    float p1 = ex2_fast(sacc[mt][nt][hi * 2 + 1]);
                    sacc[mt][nt][hi * 2] = p0;
                    sacc[mt][nt][hi * 2 + 1] = p1;
                    rs += p0 + p1;
                }
                lrow[mt][hi] += rs;
            }

        // O += P V
#pragma unroll
        for (int ksv = 0; ksv < 2; ksv++) {
            uint32_t pa[2][4];
#pragma unroll
            for (int mt = 0; mt < 2; mt++) {
                pa[mt][0] = pack_bf(sacc[mt][2 * ksv][0], sacc[mt][2 * ksv][1]);
                pa[mt][1] = pack_bf(sacc[mt][2 * ksv][2], sacc[mt][2 * ksv][3]);
                pa[mt][2] = pack_bf(sacc[mt][2 * ksv + 1][0], sacc[mt][2 * ksv + 1][1]);
                pa[mt][3] = pack_bf(sacc[mt][2 * ksv + 1][2], sacc[mt][2 * ksv + 1][3]);
            }
            uint32_t vb[4][2];
            int kkv = kc * 32 + ksv * 16;
#pragma unroll
            for (int p = 0; p < 2; p++) {
                uint32_t r4[4];
                ldsm_x4(r4, vBase + ((p * 16 + brow) * 264 + kkv + bcol) * 2);
                vb[2 * p][0] = r4[0]; vb[2 * p][1] = r4[1];
                vb[2 * p + 1][0] = r4[2]; vb[2 * p + 1][1] = r4[3];
            }
#pragma unroll
            for (int mt = 0; mt < 2; mt++)
#pragma unroll
                for (int nt = 0; nt < 4; nt++)
                    mma_bf16(o[mt][nt], pa[mt], vb[nt]);
        }
    }

#pragma unroll
    for (int mt = 0; mt < 2; mt++)
#pragma unroll
        for (int hi = 0; hi < 2; hi++) {
            float l = lrow[mt][hi];
            l += __shfl_xor_sync(0xffffffffu, l, 1);
            l += __shfl_xor_sync(0xffffffffu, l, 2);
            float inv = 1.0f / l;
            int r = mbase + mt * 16 + g + hi * 8;
#pragma unroll
            for (int nt = 0; nt < 4; nt++) {
                *reinterpret_cast<__nv_bfloat162*>(&sO[r * 40 + nt * 8 + t * 2]) =
                    __floats2bfloat162_rn(o[mt][nt][hi * 2] * inv, o[mt][nt][hi * 2 + 1] * inv);
            }
        }
    __syncthreads();

#pragma unroll
    for (int i = 0; i < 4; i++) {
        int li = i * 256 + tid;
        int s = li >> 2, seg = li & 3;
        size_t tok;
        if (branch == 0)
            tok = (size_t)(b * 128 + grp * 2) * 128 + s;
        else
            tok = (size_t)(b * 128 + (s & 127)) * 128 + grp * 2 + (s >> 7);
        *(uint4*)&g_h[tok * 256 + chq + seg * 8] = *(const uint4*)&sO[s * 40 + seg * 8];
    }
}

// ---------------------------------------------------------------------------
// launch
// ---------------------------------------------------------------------------
extern "C" void kernel_launch(void* const* d_in, const int* in_sizes, int n_in,
                              void* d_out, int out_size) {
    const float* x     = (const float*)d_in[0];
    const float* Wqkv  = (const float*)d_in[1];
    const float* bqkv  = (const float*)d_in[2];
    const float* Wproj = (const float*)d_in[3];
    const float* bproj = (const float*)d_in[4];
    const float* gamma = (const float*)d_in[5];
    const float* beta  = (const float*)d_in[6];
    float* out = (float*)d_out;

    cudaFuncSetAttribute(gemm0_persist, cudaFuncAttributeMaxDynamicSharedMemorySize, GEMM0_SMEM);
    cudaFuncSetAttribute(gemm1_persist, cudaFuncAttributeMaxDynamicSharedMemorySize, GEMM1_SMEM);
    cudaFuncSetAttribute(attn_kernel, cudaFuncAttributeMaxDynamicSharedMemorySize, ATTN_SMEM);

    prep_weights<<<768, 256>>>(Wqkv, Wproj);
    gemm0_persist<<<TOKENS / 128, 256, GEMM0_SMEM>>>(x, gamma, beta, bqkv);
    attn_kernel<<<4096, 256, ATTN_SMEM>>>();
    gemm1_persist<<<TOKENS / 128, 256, GEMM1_SMEM>>>(bproj, x, out);
}